// round 2
// baseline (speedup 1.0000x reference)
#include <cuda_runtime.h>
#include <math.h>
#include <stdint.h>

// Problem constants
#define B_    32
#define T_    128
#define V_    16000
#define E_    512
#define Z_    128
#define H_    1024
#define DIN_  640        // E+Z
#define ROWS_ 64         // 32 sample-pass rows + 32 teacher-forced rows
#define NBC_  125        // 16000 / 128 column tiles
#define TINYF 1.17549435e-38f

// Output layout (float32): [s_s (B*T)] [p_s (B*T*V)] [s_f (B*T)] [p_f (B*T*V)]
#define O_PS  4096
#define O_SF  65540096
#define O_PF  65544192

// ---------------- device scratch (static globals; no allocations) -------------
__device__ float d_h0[2][ROWS_*H_];
__device__ float d_h1[2][ROWS_*H_];
__device__ float d_c0[ROWS_*H_];
__device__ float d_c1[ROWS_*H_];
__device__ int   d_tok[B_];                 // current sampled token (free-running rows)
__device__ float d_logits[ROWS_*V_];
__device__ float d_pmax[ROWS_*NBC_];
__device__ float d_psum[ROWS_*NBC_];
__device__ float d_amv [ROWS_*NBC_];
__device__ int   d_ami [ROWS_*NBC_];

// ---------------- XLA-exact tanh (Eigen-style rational, elemental_ir_emitter) --
__device__ __forceinline__ float tanh_xla(float x){
  float ax = fabsf(x);
  if (ax < 0.0004f) return x;
  float xc = fminf(fmaxf(x, -7.90531110763549805f), 7.90531110763549805f);
  float x2 = xc*xc;
  float p = fmaf(x2, -2.76076847742355e-16f, 2.00018790482477e-13f);
  p = fmaf(x2, p, -8.60467152213735e-11f);
  p = fmaf(x2, p,  5.12229709037114e-08f);
  p = fmaf(x2, p,  1.48572235717979e-05f);
  p = fmaf(x2, p,  6.37261928875436e-04f);
  p = fmaf(x2, p,  4.89352455891786e-03f);
  p = xc * p;
  float q = fmaf(x2, 1.19825839466702e-06f, 1.18534705686654e-04f);
  q = fmaf(x2, q, 2.26843463243900e-03f);
  q = fmaf(x2, q, 4.89352518554385e-03f);
  return p / q;
}
// XLA logistic expander: 0.5 + 0.5*tanh(0.5x)
__device__ __forceinline__ float sigmoid_(float x){ return 0.5f + 0.5f*tanh_xla(0.5f*x); }

// ---------------- threefry2x32 (JAX-compatible) -------------------------------
__device__ __forceinline__ void tf2x32(unsigned k0, unsigned k1, unsigned x0, unsigned x1,
                                       unsigned &o0, unsigned &o1){
  unsigned k2 = k0 ^ k1 ^ 0x1BD11BDAu;
  x0 += k0; x1 += k1;
#define TFR(r) { x0 += x1; x1 = (x1<<(r)) | (x1>>(32-(r))); x1 ^= x0; }
  TFR(13) TFR(15) TFR(26) TFR(6)
  x0 += k1; x1 += k2 + 1u;
  TFR(17) TFR(29) TFR(16) TFR(24)
  x0 += k2; x1 += k0 + 2u;
  TFR(13) TFR(15) TFR(26) TFR(6)
  x0 += k0; x1 += k1 + 3u;
  TFR(17) TFR(29) TFR(16) TFR(24)
  x0 += k1; x1 += k2 + 4u;
  TFR(13) TFR(15) TFR(26) TFR(6)
  x0 += k2; x1 += k0 + 5u;
#undef TFR
  o0 = x0; o1 = x1;
}

// jax_threefry_partitionable=True (modern default): element j gets counter (0, j),
// 32-bit output = o0 ^ o1.
__device__ __forceinline__ unsigned pbits(unsigned k0, unsigned k1, unsigned j){
  unsigned o0, o1;
  tf2x32(k0, k1, 0u, j, o0, o1);
  return o0 ^ o1;
}

__device__ __forceinline__ float gumbel_from_bits(unsigned bits){
  float f = __uint_as_float((bits>>9) | 0x3f800000u) - 1.0f;
  float u = fmaxf(TINYF, f + TINYF);     // f*(1-tiny)+tiny == f+tiny in fp32
  return -logf(-logf(u));
}

// ---------------- init ---------------------------------------------------------
__global__ void k_init(){
  int i = blockIdx.x*blockDim.x + threadIdx.x;
  if (i < ROWS_*H_){ d_h0[1][i]=0.f; d_h1[1][i]=0.f; d_c0[i]=0.f; d_c1[i]=0.f; }
  if (i < B_) d_tok[i] = 1;   // START_ID
}

// ---------------- LSTM layer 0 -------------------------------------------------
// gates[64,4096] = concat(emb[tok], z, h0_old)[64,1664] @ concat(Wx0;Wh0) + b0
__global__ void __launch_bounds__(128) k_lstm0(int t, const int* __restrict__ x,
     const float* __restrict__ emb, const float* __restrict__ z,
     const float* __restrict__ Wx, const float* __restrict__ Wh,
     const float* __restrict__ b)
{
  __shared__ float As[32][32];
  __shared__ float Ws[32][4][16];
  __shared__ int   toks[32];
  const int tid = threadIdx.x;
  const int hb = blockIdx.x & 63, rb = blockIdx.x >> 6;
  const int rg = tid >> 4, hl = tid & 15;
  const int h  = hb*16 + hl;

  if (tid < 32){
    int r = rb*32 + tid;
    toks[tid] = (r < 32) ? d_tok[r] : ((t==0) ? 1 : x[(r-32)*T_ + t - 1]);
  }
  __syncthreads();

  const float* __restrict__ h0o = d_h0[(t&1)^1];
  float acc[4][4];
#pragma unroll
  for (int g=0; g<4; g++){ acc[g][0]=0.f; acc[g][1]=0.f; acc[g][2]=0.f; acc[g][3]=0.f; }

  for (int k0=0; k0<DIN_+H_; k0+=32){
#pragma unroll
    for (int i=0;i<8;i++){
      int e = i*128 + tid, kk = e>>5, rl = e&31, k = k0+kk, r = rb*32+rl;
      float v;
      if      (k < E_)   v = emb[(size_t)toks[rl]*E_ + k];
      else if (k < DIN_) v = z[(r&31)*Z_ + (k-E_)];
      else               v = h0o[r*H_ + (k-DIN_)];
      As[kk][rl] = v;
    }
#pragma unroll
    for (int i=0;i<16;i++){
      int e = i*128+tid, kk = e>>6, rem = e&63, g = rem>>4, hh = rem&15, k = k0+kk;
      const float* Wr = (k < DIN_) ? (Wx + (size_t)k*4096) : (Wh + (size_t)(k-DIN_)*4096);
      Ws[kk][g][hh] = Wr[g*H_ + hb*16 + hh];
    }
    __syncthreads();
#pragma unroll
    for (int kk=0; kk<32; kk++){
      float4 a = *(const float4*)&As[kk][rg*4];
#pragma unroll
      for (int g=0; g<4; g++){
        float w = Ws[kk][g][hl];
        acc[g][0] += a.x*w; acc[g][1] += a.y*w; acc[g][2] += a.z*w; acc[g][3] += a.w*w;
      }
    }
    __syncthreads();
  }

  float bi=b[h], bf=b[H_+h], bg=b[2*H_+h], bo=b[3*H_+h];
  float* __restrict__ h0n = d_h0[t&1];
#pragma unroll
  for (int j=0;j<4;j++){
    int r = rb*32 + rg*4 + j;
    float gi = acc[0][j]+bi, gf = acc[1][j]+bf, gg = acc[2][j]+bg, go = acc[3][j]+bo;
    float c  = d_c0[r*H_+h];
    float cn = sigmoid_(gf)*c + sigmoid_(gi)*tanh_xla(gg);
    d_c0[r*H_+h] = cn;
    h0n[r*H_+h]  = sigmoid_(go)*tanh_xla(cn);
  }
}

// ---------------- LSTM layer 1 -------------------------------------------------
__global__ void __launch_bounds__(128) k_lstm1(int t,
     const float* __restrict__ Wx, const float* __restrict__ Wh,
     const float* __restrict__ b)
{
  __shared__ float As[32][32];
  __shared__ float Ws[32][4][16];
  const int tid = threadIdx.x;
  const int hb = blockIdx.x & 63, rb = blockIdx.x >> 6;
  const int rg = tid >> 4, hl = tid & 15;
  const int h  = hb*16 + hl;

  const float* __restrict__ h0n = d_h0[t&1];
  const float* __restrict__ h1o = d_h1[(t&1)^1];
  float acc[4][4];
#pragma unroll
  for (int g=0; g<4; g++){ acc[g][0]=0.f; acc[g][1]=0.f; acc[g][2]=0.f; acc[g][3]=0.f; }

  for (int k0=0; k0<2*H_; k0+=32){
#pragma unroll
    for (int i=0;i<8;i++){
      int e = i*128 + tid, kk = e>>5, rl = e&31, k = k0+kk, r = rb*32+rl;
      As[kk][rl] = (k < H_) ? h0n[r*H_ + k] : h1o[r*H_ + (k-H_)];
    }
#pragma unroll
    for (int i=0;i<16;i++){
      int e = i*128+tid, kk = e>>6, rem = e&63, g = rem>>4, hh = rem&15, k = k0+kk;
      const float* Wr = (k < H_) ? (Wx + (size_t)k*4096) : (Wh + (size_t)(k-H_)*4096);
      Ws[kk][g][hh] = Wr[g*H_ + hb*16 + hh];
    }
    __syncthreads();
#pragma unroll
    for (int kk=0; kk<32; kk++){
      float4 a = *(const float4*)&As[kk][rg*4];
#pragma unroll
      for (int g=0; g<4; g++){
        float w = Ws[kk][g][hl];
        acc[g][0] += a.x*w; acc[g][1] += a.y*w; acc[g][2] += a.z*w; acc[g][3] += a.w*w;
      }
    }
    __syncthreads();
  }

  float bi=b[h], bf=b[H_+h], bg=b[2*H_+h], bo=b[3*H_+h];
  float* __restrict__ h1n = d_h1[t&1];
#pragma unroll
  for (int j=0;j<4;j++){
    int r = rb*32 + rg*4 + j;
    float gi = acc[0][j]+bi, gf = acc[1][j]+bf, gg = acc[2][j]+bg, go = acc[3][j]+bo;
    float c  = d_c1[r*H_+h];
    float cn = sigmoid_(gf)*c + sigmoid_(gi)*tanh_xla(gg);
    d_c1[r*H_+h] = cn;
    h1n[r*H_+h]  = sigmoid_(go)*tanh_xla(cn);
  }
}

// ---------------- logits GEMM + per-block softmax partials ---------------------
__global__ void __launch_bounds__(256) k_logits(int t,
     const float* __restrict__ W, const float* __restrict__ bout)
{
  __shared__ float As[32][64];
  __shared__ float Ws[32][128];
  const int tid = threadIdx.x, cb = blockIdx.x;
  const int rg = tid>>4, cg = tid&15;
  const float* __restrict__ h1n = d_h1[t&1];

  float acc[4][8];
#pragma unroll
  for (int r=0;r<4;r++)
#pragma unroll
    for (int c=0;c<8;c++) acc[r][c]=0.f;

  for (int k0=0;k0<H_;k0+=32){
#pragma unroll
    for (int i=0;i<8;i++){ int e=i*256+tid, kk=e>>6, rl=e&63; As[kk][rl]=h1n[rl*H_+k0+kk]; }
#pragma unroll
    for (int i=0;i<16;i++){ int e=i*256+tid, kk=e>>7, c=e&127;
      Ws[kk][c] = W[(size_t)(k0+kk)*V_ + cb*128 + c]; }
    __syncthreads();
#pragma unroll
    for (int kk=0;kk<32;kk++){
      float4 a  = *(const float4*)&As[kk][rg*4];
      float4 w0 = *(const float4*)&Ws[kk][cg*8];
      float4 w1 = *(const float4*)&Ws[kk][cg*8+4];
      acc[0][0]+=a.x*w0.x; acc[0][1]+=a.x*w0.y; acc[0][2]+=a.x*w0.z; acc[0][3]+=a.x*w0.w;
      acc[0][4]+=a.x*w1.x; acc[0][5]+=a.x*w1.y; acc[0][6]+=a.x*w1.z; acc[0][7]+=a.x*w1.w;
      acc[1][0]+=a.y*w0.x; acc[1][1]+=a.y*w0.y; acc[1][2]+=a.y*w0.z; acc[1][3]+=a.y*w0.w;
      acc[1][4]+=a.y*w1.x; acc[1][5]+=a.y*w1.y; acc[1][6]+=a.y*w1.z; acc[1][7]+=a.y*w1.w;
      acc[2][0]+=a.z*w0.x; acc[2][1]+=a.z*w0.y; acc[2][2]+=a.z*w0.z; acc[2][3]+=a.z*w0.w;
      acc[2][4]+=a.z*w1.x; acc[2][5]+=a.z*w1.y; acc[2][6]+=a.z*w1.z; acc[2][7]+=a.z*w1.w;
      acc[3][0]+=a.w*w0.x; acc[3][1]+=a.w*w0.y; acc[3][2]+=a.w*w0.z; acc[3][3]+=a.w*w0.w;
      acc[3][4]+=a.w*w1.x; acc[3][5]+=a.w*w1.y; acc[3][6]+=a.w*w1.z; acc[3][7]+=a.w*w1.w;
    }
    __syncthreads();
  }

  float m[4], s[4];
#pragma unroll
  for (int r=0;r<4;r++){
    m[r] = -INFINITY;
#pragma unroll
    for (int c=0;c<8;c++){
      int col = cb*128 + cg*8 + c;
      acc[r][c] += bout[col];
      m[r] = fmaxf(m[r], acc[r][c]);
    }
  }
#pragma unroll
  for (int msk=8; msk>=1; msk>>=1)
#pragma unroll
    for (int r=0;r<4;r++) m[r] = fmaxf(m[r], __shfl_xor_sync(0xffffffffu, m[r], msk));
#pragma unroll
  for (int r=0;r<4;r++){
    s[r] = 0.f;
#pragma unroll
    for (int c=0;c<8;c++) s[r] += expf(acc[r][c] - m[r]);
  }
#pragma unroll
  for (int msk=8; msk>=1; msk>>=1)
#pragma unroll
    for (int r=0;r<4;r++) s[r] += __shfl_xor_sync(0xffffffffu, s[r], msk);

#pragma unroll
  for (int r=0;r<4;r++){
    int row = rg*4 + r;
#pragma unroll
    for (int c=0;c<8;c++) d_logits[(size_t)row*V_ + cb*128 + cg*8 + c] = acc[r][c];
    if (cg==0){ d_pmax[row*NBC_+cb] = m[r]; d_psum[row*NBC_+cb] = s[r]; }
  }
}

// ---------------- p = exp(logp), gumbel sampling partial argmax -----------------
__global__ void __launch_bounds__(256) k_sample(int t, float* __restrict__ out)
{
  __shared__ float sM[ROWS_], sL[ROWS_];
  const int tid = threadIdx.x, cb = blockIdx.x;

  if (tid < ROWS_){
    float m = -INFINITY;
    for (int j=0;j<NBC_;j++) m = fmaxf(m, d_pmax[tid*NBC_+j]);
    float s = 0.f;
    for (int j=0;j<NBC_;j++) s += d_psum[tid*NBC_+j]*expf(d_pmax[tid*NBC_+j]-m);
    sM[tid] = m; sL[tid] = logf(s);
  }
  __syncthreads();

  const int pass = tid>>7, bp = (tid>>3)&15, sub = tid&7;
  unsigned ka0,ka1,k0,k1;
  tf2x32(0u, 42u, 0u, (unsigned)pass, ka0, ka1);   // fold_in(key(42), stream)
  tf2x32(ka0, ka1, 0u, (unsigned)t,  k0,  k1);     // fold_in(., t)

  const int rlo = pass*32 + bp, rhi = rlo + 16;
  const float Mlo = sM[rlo], Llo = sL[rlo], Mhi = sM[rhi], Lhi = sL[rhi];
  const float* __restrict__ loglo = d_logits + (size_t)rlo*V_;
  const float* __restrict__ loghi = d_logits + (size_t)rhi*V_;
  size_t baseLo = (pass==0) ? (size_t)O_PS + ((size_t)rlo*T_ + t)*V_
                            : (size_t)O_PF + ((size_t)(rlo-32)*T_ + t)*V_;
  size_t baseHi = (pass==0) ? (size_t)O_PS + ((size_t)rhi*T_ + t)*V_
                            : (size_t)O_PF + ((size_t)(rhi-32)*T_ + t)*V_;

  float bvlo = -INFINITY, bvhi = -INFINITY;
  int   bilo = 0x7fffffff, bihi = 0x7fffffff;

  for (int j=0;j<16;j++){
    int v = cb*128 + j*8 + sub;
    // partitionable threefry: per-element counter (0, b*V+v), bits = o0^o1
    unsigned blo = pbits(k0, k1, (unsigned)(bp*V_ + v));
    unsigned bhi = pbits(k0, k1, (unsigned)((bp+16)*V_ + v));
    {
      float g = gumbel_from_bits(blo);
      float lp = (loglo[v] - Mlo) - Llo;
      out[baseLo + v] = expf(lp);
      float val = lp + g;
      if (val > bvlo){ bvlo = val; bilo = v; }
    }
    {
      float g = gumbel_from_bits(bhi);
      float lp = (loghi[v] - Mhi) - Lhi;
      out[baseHi + v] = expf(lp);
      float val = lp + g;
      if (val > bvhi){ bvhi = val; bihi = v; }
    }
  }
#pragma unroll
  for (int msk=4; msk>=1; msk>>=1){
    float ov; int oi;
    ov = __shfl_xor_sync(0xffffffffu, bvlo, msk);
    oi = __shfl_xor_sync(0xffffffffu, bilo, msk);
    if (ov > bvlo || (ov == bvlo && oi < bilo)){ bvlo = ov; bilo = oi; }
    ov = __shfl_xor_sync(0xffffffffu, bvhi, msk);
    oi = __shfl_xor_sync(0xffffffffu, bihi, msk);
    if (ov > bvhi || (ov == bvhi && oi < bihi)){ bvhi = ov; bihi = oi; }
  }
  if (sub == 0){
    d_amv[rlo*NBC_+cb] = bvlo; d_ami[rlo*NBC_+cb] = bilo;
    d_amv[rhi*NBC_+cb] = bvhi; d_ami[rhi*NBC_+cb] = bihi;
  }
}

// ---------------- final argmax + token update ----------------------------------
__global__ void __launch_bounds__(128) k_argmax(int t, float* __restrict__ out)
{
  __shared__ float sv[128];
  __shared__ int   si[128];
  const int row = blockIdx.x, tid = threadIdx.x;
  sv[tid] = (tid < NBC_) ? d_amv[row*NBC_+tid] : -INFINITY;
  si[tid] = (tid < NBC_) ? d_ami[row*NBC_+tid] : 0x7fffffff;
  __syncthreads();
  for (int s=64; s>0; s>>=1){
    if (tid < s){
      float ov = sv[tid+s]; int oi = si[tid+s];
      if (ov > sv[tid] || (ov == sv[tid] && oi < si[tid])){ sv[tid]=ov; si[tid]=oi; }
    }
    __syncthreads();
  }
  if (tid == 0){
    int idx = si[0];
    int pass = row>>5, b = row&31;
    if (pass == 0){ out[(size_t)b*T_ + t] = (float)idx; d_tok[b] = idx; }
    else          { out[(size_t)O_SF + (size_t)b*T_ + t] = (float)idx; }
  }
}

// ---------------- launch -------------------------------------------------------
extern "C" void kernel_launch(void* const* d_in, const int* in_sizes, int n_in,
                              void* d_out, int out_size)
{
  const int*   x    = (const int*)  d_in[0];
  const float* z    = (const float*)d_in[1];
  const float* emb  = (const float*)d_in[2];
  const float* Wx0  = (const float*)d_in[3];
  const float* Wh0  = (const float*)d_in[4];
  const float* b0   = (const float*)d_in[5];
  const float* Wx1  = (const float*)d_in[6];
  const float* Wh1  = (const float*)d_in[7];
  const float* b1   = (const float*)d_in[8];
  const float* Wout = (const float*)d_in[9];
  const float* bout = (const float*)d_in[10];
  float* out = (float*)d_out;

  k_init<<<256, 256>>>();
  for (int t = 0; t < T_; t++){
    k_lstm0 <<<128, 128>>>(t, x, emb, z, Wx0, Wh0, b0);
    k_lstm1 <<<128, 128>>>(t, Wx1, Wh1, b1);
    k_logits<<<NBC_, 256>>>(t, Wout, bout);
    k_sample<<<NBC_, 256>>>(t, out);
    k_argmax<<<ROWS_, 128>>>(t, out);
  }
}

// round 3
// speedup vs baseline: 2.7304x; 2.7304x over previous
#include <cuda_runtime.h>
#include <math.h>
#include <stdint.h>

// Problem constants
#define B_    32
#define T_    128
#define V_    16000
#define E_    512
#define Z_    128
#define H_    1024
#define DIN_  640        // E+Z
#define ROWS_ 64         // 32 sample-pass rows + 32 teacher-forced rows
#define NBC_  125        // 16000 / 128 column tiles
#define TINYF 1.17549435e-38f

// Output layout (float32): [s_s (B*T)] [p_s (B*T*V)] [s_f (B*T)] [p_f (B*T*V)]
#define O_PS  4096
#define O_SF  65540096
#define O_PF  65544192

// ---------------- device scratch (static globals; no allocations) -------------
// Transposed A for LSTM0: rows: [0,512) emb-gather, [512,640) z, [640,1664) h0^T
__device__ float d_A0T[(DIN_+H_)*ROWS_];
__device__ float d_h1T[H_*ROWS_];           // h1^T (for lstm1 next step + logits)
__device__ float d_c0[ROWS_*H_];
__device__ float d_c1[ROWS_*H_];
__device__ float d_gp[2][ROWS_*4*H_];       // K-split gate partials
__device__ int   d_tok[B_];                 // current sampled token (free rows)
__device__ float d_logits[ROWS_*V_];
__device__ float d_pmax[ROWS_*NBC_];
__device__ float d_psum[ROWS_*NBC_];
__device__ float d_amv [ROWS_*NBC_];
__device__ int   d_ami [ROWS_*NBC_];

// ---------------- XLA-exact tanh (Eigen-style rational) ------------------------
__device__ __forceinline__ float tanh_xla(float x){
  float ax = fabsf(x);
  if (ax < 0.0004f) return x;
  float xc = fminf(fmaxf(x, -7.90531110763549805f), 7.90531110763549805f);
  float x2 = xc*xc;
  float p = fmaf(x2, -2.76076847742355e-16f, 2.00018790482477e-13f);
  p = fmaf(x2, p, -8.60467152213735e-11f);
  p = fmaf(x2, p,  5.12229709037114e-08f);
  p = fmaf(x2, p,  1.48572235717979e-05f);
  p = fmaf(x2, p,  6.37261928875436e-04f);
  p = fmaf(x2, p,  4.89352455891786e-03f);
  p = xc * p;
  float q = fmaf(x2, 1.19825839466702e-06f, 1.18534705686654e-04f);
  q = fmaf(x2, q, 2.26843463243900e-03f);
  q = fmaf(x2, q, 4.89352518554385e-03f);
  return p / q;
}
__device__ __forceinline__ float sigmoid_(float x){ return 0.5f + 0.5f*tanh_xla(0.5f*x); }

// ---------------- threefry2x32 (JAX partitionable) ----------------------------
__device__ __forceinline__ void tf2x32(unsigned k0, unsigned k1, unsigned x0, unsigned x1,
                                       unsigned &o0, unsigned &o1){
  unsigned k2 = k0 ^ k1 ^ 0x1BD11BDAu;
  x0 += k0; x1 += k1;
#define TFR(r) { x0 += x1; x1 = (x1<<(r)) | (x1>>(32-(r))); x1 ^= x0; }
  TFR(13) TFR(15) TFR(26) TFR(6)
  x0 += k1; x1 += k2 + 1u;
  TFR(17) TFR(29) TFR(16) TFR(24)
  x0 += k2; x1 += k0 + 2u;
  TFR(13) TFR(15) TFR(26) TFR(6)
  x0 += k0; x1 += k1 + 3u;
  TFR(17) TFR(29) TFR(16) TFR(24)
  x0 += k1; x1 += k2 + 4u;
  TFR(13) TFR(15) TFR(26) TFR(6)
  x0 += k2; x1 += k0 + 5u;
#undef TFR
  o0 = x0; o1 = x1;
}
__device__ __forceinline__ unsigned pbits(unsigned k0, unsigned k1, unsigned j){
  unsigned o0, o1; tf2x32(k0, k1, 0u, j, o0, o1); return o0 ^ o1;
}
__device__ __forceinline__ float gumbel_from_bits(unsigned bits){
  float f = __uint_as_float((bits>>9) | 0x3f800000u) - 1.0f;
  float u = fmaxf(TINYF, f + TINYF);
  return -logf(-logf(u));
}

// ---------------- init ---------------------------------------------------------
__global__ void k_init(const float* __restrict__ z, const float* __restrict__ emb){
  int i = blockIdx.x*blockDim.x + threadIdx.x;
  if (i < ROWS_*H_){
    d_A0T[DIN_*ROWS_ + i] = 0.f;    // h0^T = 0
    d_h1T[i] = 0.f;
    d_c0[i] = 0.f; d_c1[i] = 0.f;
  }
  if (i < Z_*ROWS_){                // z rows of A0T (constant across steps)
    int zz = i >> 6, r = i & 63;
    d_A0T[(E_+zz)*ROWS_ + r] = z[(r&31)*Z_ + zz];
  }
  if (i < E_*ROWS_){                // initial emb gather: token = START (=1) everywhere
    int k = i >> 6, r = i & 63;
    d_A0T[(size_t)k*ROWS_ + r] = emb[(size_t)E_ + k];
  }
  if (i < B_) d_tok[i] = 1;
}

// ---------------- generic K-split GEMM: [64 x K] (transposed A) @ [K x 4096] ---
// grid 128 = 64 col-tiles x 2 K-splits; block 256; tile 64r x 64c; thread 4x4.
__global__ void __launch_bounds__(256) k_gemm(
    const float* __restrict__ A1, int alen1, const float* __restrict__ A2,
    const float* __restrict__ W1, int wlen1, const float* __restrict__ W2,
    int kPerSplit, float* __restrict__ gp)
{
  __shared__ float As[32][64];
  __shared__ float Ws[32][64];
  const int tid = threadIdx.x;
  const int ct = blockIdx.x & 63, sp = blockIdx.x >> 6;
  const int rg = tid >> 4, cg = tid & 15;
  const int kbeg = sp * kPerSplit;
  const int nch = kPerSplit >> 5;
  const int cbase = ct * 64;

  float acc[4][4];
#pragma unroll
  for (int j=0;j<4;j++){ acc[j][0]=0.f; acc[j][1]=0.f; acc[j][2]=0.f; acc[j][3]=0.f; }

  float4 ra[2], rw[2];
  // prefetch chunk 0
  {
    int k0 = kbeg;
    const float* ap = (k0 < alen1) ? (A1 + (size_t)k0*64) : (A2 + (size_t)(k0-alen1)*64);
    const float* wp = (k0 < wlen1) ? (W1 + (size_t)k0*4096) : (W2 + (size_t)(k0-wlen1)*4096);
#pragma unroll
    for (int i=0;i<2;i++) ra[i] = ((const float4*)ap)[i*256 + tid];
#pragma unroll
    for (int i=0;i<2;i++){
      int f = i*256 + tid, kk = f >> 4, c4 = (f & 15) * 4;
      rw[i] = *(const float4*)(wp + (size_t)kk*4096 + cbase + c4);
    }
  }
#pragma unroll
  for (int i=0;i<2;i++){
    int f = i*256 + tid, e = f*4, kk = e >> 6, rl = e & 63;
    *(float4*)&As[kk][rl] = ra[i];
  }
#pragma unroll
  for (int i=0;i<2;i++){
    int f = i*256 + tid, kk = f >> 4, c4 = (f & 15) * 4;
    *(float4*)&Ws[kk][c4] = rw[i];
  }
  __syncthreads();

  for (int ci = 0; ci < nch; ci++){
    if (ci+1 < nch){
      int k0 = kbeg + (ci+1)*32;
      const float* ap = (k0 < alen1) ? (A1 + (size_t)k0*64) : (A2 + (size_t)(k0-alen1)*64);
      const float* wp = (k0 < wlen1) ? (W1 + (size_t)k0*4096) : (W2 + (size_t)(k0-wlen1)*4096);
#pragma unroll
      for (int i=0;i<2;i++) ra[i] = ((const float4*)ap)[i*256 + tid];
#pragma unroll
      for (int i=0;i<2;i++){
        int f = i*256 + tid, kk = f >> 4, c4 = (f & 15) * 4;
        rw[i] = *(const float4*)(wp + (size_t)kk*4096 + cbase + c4);
      }
    }
#pragma unroll
    for (int kk=0; kk<32; kk++){
      float4 a = *(const float4*)&As[kk][rg*4];
      float4 w = *(const float4*)&Ws[kk][cg*4];
      acc[0][0]+=a.x*w.x; acc[0][1]+=a.x*w.y; acc[0][2]+=a.x*w.z; acc[0][3]+=a.x*w.w;
      acc[1][0]+=a.y*w.x; acc[1][1]+=a.y*w.y; acc[1][2]+=a.y*w.z; acc[1][3]+=a.y*w.w;
      acc[2][0]+=a.z*w.x; acc[2][1]+=a.z*w.y; acc[2][2]+=a.z*w.z; acc[2][3]+=a.z*w.w;
      acc[3][0]+=a.w*w.x; acc[3][1]+=a.w*w.y; acc[3][2]+=a.w*w.z; acc[3][3]+=a.w*w.w;
    }
    __syncthreads();
    if (ci+1 < nch){
#pragma unroll
      for (int i=0;i<2;i++){
        int f = i*256 + tid, e = f*4, kk = e >> 6, rl = e & 63;
        *(float4*)&As[kk][rl] = ra[i];
      }
#pragma unroll
      for (int i=0;i<2;i++){
        int f = i*256 + tid, kk = f >> 4, c4 = (f & 15) * 4;
        *(float4*)&Ws[kk][c4] = rw[i];
      }
      __syncthreads();
    }
  }

  float* op = gp + (size_t)sp*ROWS_*4096;
#pragma unroll
  for (int j=0;j<4;j++){
    int r = rg*4 + j;
    *(float4*)(op + (size_t)r*4096 + cbase + cg*4) = make_float4(acc[j][0],acc[j][1],acc[j][2],acc[j][3]);
  }
}

// ---------------- bias + LSTM activation; writes h^T --------------------------
// grid 128, block 512: idx -> h fast, r slow.
__global__ void __launch_bounds__(512) k_act(const float* __restrict__ b,
    float* __restrict__ c, float* __restrict__ hT)
{
  int idx = blockIdx.x*512 + threadIdx.x;      // 65536
  int h = idx & 1023, r = idx >> 10;
  const float* g0 = d_gp[0] + (size_t)r*4096;
  const float* g1 = d_gp[1] + (size_t)r*4096;
  float gi = g0[h]        + g1[h]        + b[h];
  float gf = g0[1024+h]   + g1[1024+h]   + b[1024+h];
  float gg = g0[2048+h]   + g1[2048+h]   + b[2048+h];
  float go = g0[3072+h]   + g1[3072+h]   + b[3072+h];
  float cv = c[(size_t)r*1024 + h];
  float cn = sigmoid_(gf)*cv + sigmoid_(gi)*tanh_xla(gg);
  c[(size_t)r*1024 + h] = cn;
  hT[(size_t)h*64 + r]  = sigmoid_(go)*tanh_xla(cn);
}

// ---------------- logits GEMM + per-block softmax partials ---------------------
// C[64,16000] = h1[64,1024] @ Wout + bout (A from h1^T)
__global__ void __launch_bounds__(256) k_logits(
     const float* __restrict__ W, const float* __restrict__ bout)
{
  __shared__ float As[32][64];
  __shared__ float Ws[32][128];
  const int tid = threadIdx.x, cb = blockIdx.x;
  const int rg = tid>>4, cg = tid&15;

  float acc[4][8];
#pragma unroll
  for (int r=0;r<4;r++)
#pragma unroll
    for (int c=0;c<8;c++) acc[r][c]=0.f;

  float4 ra[2], rw[4];
  {
    const float* ap = d_h1T;
#pragma unroll
    for (int i=0;i<2;i++) ra[i] = ((const float4*)ap)[i*256 + tid];
#pragma unroll
    for (int i=0;i<4;i++){
      int f = i*256 + tid, kk = f >> 5, c4 = (f & 31) * 4;
      rw[i] = *(const float4*)(W + (size_t)kk*V_ + cb*128 + c4);
    }
  }
#pragma unroll
  for (int i=0;i<2;i++){ int f=i*256+tid, e=f*4, kk=e>>6, rl=e&63; *(float4*)&As[kk][rl]=ra[i]; }
#pragma unroll
  for (int i=0;i<4;i++){ int f=i*256+tid, kk=f>>5, c4=(f&31)*4; *(float4*)&Ws[kk][c4]=rw[i]; }
  __syncthreads();

  for (int ci=0; ci<32; ci++){
    if (ci+1 < 32){
      int k0 = (ci+1)*32;
      const float* ap = d_h1T + (size_t)k0*64;
#pragma unroll
      for (int i=0;i<2;i++) ra[i] = ((const float4*)ap)[i*256 + tid];
#pragma unroll
      for (int i=0;i<4;i++){
        int f = i*256 + tid, kk = f >> 5, c4 = (f & 31) * 4;
        rw[i] = *(const float4*)(W + (size_t)(k0+kk)*V_ + cb*128 + c4);
      }
    }
#pragma unroll
    for (int kk=0;kk<32;kk++){
      float4 a  = *(const float4*)&As[kk][rg*4];
      float4 w0 = *(const float4*)&Ws[kk][cg*8];
      float4 w1 = *(const float4*)&Ws[kk][cg*8+4];
      acc[0][0]+=a.x*w0.x; acc[0][1]+=a.x*w0.y; acc[0][2]+=a.x*w0.z; acc[0][3]+=a.x*w0.w;
      acc[0][4]+=a.x*w1.x; acc[0][5]+=a.x*w1.y; acc[0][6]+=a.x*w1.z; acc[0][7]+=a.x*w1.w;
      acc[1][0]+=a.y*w0.x; acc[1][1]+=a.y*w0.y; acc[1][2]+=a.y*w0.z; acc[1][3]+=a.y*w0.w;
      acc[1][4]+=a.y*w1.x; acc[1][5]+=a.y*w1.y; acc[1][6]+=a.y*w1.z; acc[1][7]+=a.y*w1.w;
      acc[2][0]+=a.z*w0.x; acc[2][1]+=a.z*w0.y; acc[2][2]+=a.z*w0.z; acc[2][3]+=a.z*w0.w;
      acc[2][4]+=a.z*w1.x; acc[2][5]+=a.z*w1.y; acc[2][6]+=a.z*w1.z; acc[2][7]+=a.z*w1.w;
      acc[3][0]+=a.w*w0.x; acc[3][1]+=a.w*w0.y; acc[3][2]+=a.w*w0.z; acc[3][3]+=a.w*w0.w;
      acc[3][4]+=a.w*w1.x; acc[3][5]+=a.w*w1.y; acc[3][6]+=a.w*w1.z; acc[3][7]+=a.w*w1.w;
    }
    __syncthreads();
    if (ci+1 < 32){
#pragma unroll
      for (int i=0;i<2;i++){ int f=i*256+tid, e=f*4, kk=e>>6, rl=e&63; *(float4*)&As[kk][rl]=ra[i]; }
#pragma unroll
      for (int i=0;i<4;i++){ int f=i*256+tid, kk=f>>5, c4=(f&31)*4; *(float4*)&Ws[kk][c4]=rw[i]; }
      __syncthreads();
    }
  }

  float m[4], s[4];
#pragma unroll
  for (int r=0;r<4;r++){
    m[r] = -INFINITY;
#pragma unroll
    for (int c=0;c<8;c++){
      int col = cb*128 + cg*8 + c;
      acc[r][c] += bout[col];
      m[r] = fmaxf(m[r], acc[r][c]);
    }
  }
#pragma unroll
  for (int msk=8; msk>=1; msk>>=1)
#pragma unroll
    for (int r=0;r<4;r++) m[r] = fmaxf(m[r], __shfl_xor_sync(0xffffffffu, m[r], msk));
#pragma unroll
  for (int r=0;r<4;r++){
    s[r] = 0.f;
#pragma unroll
    for (int c=0;c<8;c++) s[r] += __expf(acc[r][c] - m[r]);
  }
#pragma unroll
  for (int msk=8; msk>=1; msk>>=1)
#pragma unroll
    for (int r=0;r<4;r++) s[r] += __shfl_xor_sync(0xffffffffu, s[r], msk);

#pragma unroll
  for (int r=0;r<4;r++){
    int row = rg*4 + r;
#pragma unroll
    for (int c=0;c<8;c+=4)
      *(float4*)&d_logits[(size_t)row*V_ + cb*128 + cg*8 + c] =
          make_float4(acc[r][c],acc[r][c+1],acc[r][c+2],acc[r][c+3]);
    if (cg==0){ d_pmax[row*NBC_+cb] = m[r]; d_psum[row*NBC_+cb] = s[r]; }
  }
}

// ---------------- p = exp(logp), gumbel sampling partial argmax -----------------
__global__ void __launch_bounds__(256) k_sample(int t, float* __restrict__ out)
{
  __shared__ float sM[ROWS_], sL[ROWS_];
  const int tid = threadIdx.x, cb = blockIdx.x;

  if (tid < ROWS_){
    float m = -INFINITY;
    for (int j=0;j<NBC_;j++) m = fmaxf(m, d_pmax[tid*NBC_+j]);
    float s = 0.f;
    for (int j=0;j<NBC_;j++) s += d_psum[tid*NBC_+j]*__expf(d_pmax[tid*NBC_+j]-m);
    sM[tid] = m; sL[tid] = logf(s);
  }
  __syncthreads();

  const int pass = tid>>7, bp = (tid>>3)&15, sub = tid&7;
  unsigned ka0,ka1,k0,k1;
  tf2x32(0u, 42u, 0u, (unsigned)pass, ka0, ka1);
  tf2x32(ka0, ka1, 0u, (unsigned)t,  k0,  k1);

  const int rlo = pass*32 + bp, rhi = rlo + 16;
  const float Mlo = sM[rlo], Llo = sL[rlo], Mhi = sM[rhi], Lhi = sL[rhi];
  const float* __restrict__ loglo = d_logits + (size_t)rlo*V_;
  const float* __restrict__ loghi = d_logits + (size_t)rhi*V_;
  size_t baseLo = (pass==0) ? (size_t)O_PS + ((size_t)rlo*T_ + t)*V_
                            : (size_t)O_PF + ((size_t)(rlo-32)*T_ + t)*V_;
  size_t baseHi = (pass==0) ? (size_t)O_PS + ((size_t)rhi*T_ + t)*V_
                            : (size_t)O_PF + ((size_t)(rhi-32)*T_ + t)*V_;

  float bvlo = -INFINITY, bvhi = -INFINITY;
  int   bilo = 0x7fffffff, bihi = 0x7fffffff;

  for (int j=0;j<16;j++){
    int v = cb*128 + j*8 + sub;
    unsigned blo = pbits(k0, k1, (unsigned)(bp*V_ + v));
    unsigned bhi = pbits(k0, k1, (unsigned)((bp+16)*V_ + v));
    {
      float g = gumbel_from_bits(blo);
      float lp = (loglo[v] - Mlo) - Llo;
      out[baseLo + v] = __expf(lp);
      float val = lp + g;
      if (val > bvlo){ bvlo = val; bilo = v; }
    }
    {
      float g = gumbel_from_bits(bhi);
      float lp = (loghi[v] - Mhi) - Lhi;
      out[baseHi + v] = __expf(lp);
      float val = lp + g;
      if (val > bvhi){ bvhi = val; bihi = v; }
    }
  }
#pragma unroll
  for (int msk=4; msk>=1; msk>>=1){
    float ov; int oi;
    ov = __shfl_xor_sync(0xffffffffu, bvlo, msk);
    oi = __shfl_xor_sync(0xffffffffu, bilo, msk);
    if (ov > bvlo || (ov == bvlo && oi < bilo)){ bvlo = ov; bilo = oi; }
    ov = __shfl_xor_sync(0xffffffffu, bvhi, msk);
    oi = __shfl_xor_sync(0xffffffffu, bihi, msk);
    if (ov > bvhi || (ov == bvhi && oi < bihi)){ bvhi = ov; bihi = oi; }
  }
  if (sub == 0){
    d_amv[rlo*NBC_+cb] = bvlo; d_ami[rlo*NBC_+cb] = bilo;
    d_amv[rhi*NBC_+cb] = bvhi; d_ami[rhi*NBC_+cb] = bihi;
  }
}

// ------- final argmax + token update + NEXT step's embedding gather ------------
__global__ void __launch_bounds__(128) k_argprep(int t, const int* __restrict__ x,
    const float* __restrict__ emb, float* __restrict__ out)
{
  __shared__ float sv[128];
  __shared__ int   si[128];
  __shared__ int   stok;
  const int row = blockIdx.x, tid = threadIdx.x;
  sv[tid] = (tid < NBC_) ? d_amv[row*NBC_+tid] : -INFINITY;
  si[tid] = (tid < NBC_) ? d_ami[row*NBC_+tid] : 0x7fffffff;
  __syncthreads();
  for (int s=64; s>0; s>>=1){
    if (tid < s){
      float ov = sv[tid+s]; int oi = si[tid+s];
      if (ov > sv[tid] || (ov == sv[tid] && oi < si[tid])){ sv[tid]=ov; si[tid]=oi; }
    }
    __syncthreads();
  }
  if (tid == 0){
    int idx = si[0];
    int pass = row>>5, b = row&31;
    if (pass == 0){ out[(size_t)b*T_ + t] = (float)idx; d_tok[b] = idx; stok = idx; }
    else          { out[(size_t)O_SF + (size_t)b*T_ + t] = (float)idx;
                    stok = x[(size_t)b*T_ + t]; }   // teacher input for step t+1
  }
  __syncthreads();
  const int tok = stok;
  for (int k = tid; k < E_; k += 128)
    d_A0T[(size_t)k*ROWS_ + row] = emb[(size_t)tok*E_ + k];
}

// ---------------- launch -------------------------------------------------------
extern "C" void kernel_launch(void* const* d_in, const int* in_sizes, int n_in,
                              void* d_out, int out_size)
{
  const int*   x    = (const int*)  d_in[0];
  const float* z    = (const float*)d_in[1];
  const float* emb  = (const float*)d_in[2];
  const float* Wx0  = (const float*)d_in[3];
  const float* Wh0  = (const float*)d_in[4];
  const float* b0   = (const float*)d_in[5];
  const float* Wx1  = (const float*)d_in[6];
  const float* Wh1  = (const float*)d_in[7];
  const float* b1   = (const float*)d_in[8];
  const float* Wout = (const float*)d_in[9];
  const float* bout = (const float*)d_in[10];
  float* out = (float*)d_out;

  float* pA0T; cudaGetSymbolAddress((void**)&pA0T, d_A0T);
  float* ph1T; cudaGetSymbolAddress((void**)&ph1T, d_h1T);
  float* pc0;  cudaGetSymbolAddress((void**)&pc0,  d_c0);
  float* pc1;  cudaGetSymbolAddress((void**)&pc1,  d_c1);
  float* pgp;  cudaGetSymbolAddress((void**)&pgp,  d_gp);

  k_init<<<256, 256>>>(z, emb);
  for (int t = 0; t < T_; t++){
    // LSTM0: A = A0T (contiguous, len 1664), W = [Wx0;Wh0] split at 640
    k_gemm<<<128, 256>>>(pA0T, 1<<30, (const float*)nullptr,
                         Wx0, DIN_, Wh0, 832, pgp);
    k_act <<<128, 512>>>(b0, pc0, pA0T + (size_t)DIN_*ROWS_);
    // LSTM1: A = [h0T (in A0T+640*64); h1T], W = [Wx1;Wh1] split at 1024
    k_gemm<<<128, 256>>>(pA0T + (size_t)DIN_*ROWS_, H_, ph1T,
                         Wx1, H_, Wh1, 1024, pgp);
    k_act <<<128, 512>>>(b1, pc1, ph1T);
    k_logits<<<NBC_, 256>>>(Wout, bout);
    k_sample<<<NBC_, 256>>>(t, out);
    k_argprep<<<ROWS_, 128>>>(t, x, emb, out);
  }
}

// round 4
// speedup vs baseline: 2.9584x; 1.0835x over previous
#include <cuda_runtime.h>
#include <math.h>
#include <stdint.h>

typedef unsigned long long ull;

// Problem constants
#define B_    32
#define T_    128
#define V_    16000
#define E_    512
#define Z_    128
#define H_    1024
#define DIN_  640        // E+Z
#define ROWS_ 64         // 32 sample-pass rows + 32 teacher-forced rows
#define NBC_  125        // 16000/128 sampling col tiles
#define NBCL_ 250        // 16000/64 logits col tiles
#define TINYF 1.17549435e-38f

// Output layout (float32): [s_s (B*T)] [p_s (B*T*V)] [s_f (B*T)] [p_f (B*T*V)]
#define O_PS  4096
#define O_SF  65540096
#define O_PF  65544192

// ---------------- device scratch (static globals; no allocations) -------------
__device__ float d_A0T[(DIN_+H_)*ROWS_];    // [k][64r]; emb rows, z rows, h0^T
__device__ float d_h1T[H_*ROWS_];
__device__ float d_c0[ROWS_*H_];
__device__ float d_c1[ROWS_*H_];
__device__ float d_gp[4][ROWS_*4*H_];       // 4-way K-split gate partials
__device__ int   d_tok[B_];
__device__ float d_logits[ROWS_*V_];
__device__ float d_pmax[ROWS_*NBCL_];
__device__ float d_psum[ROWS_*NBCL_];
__device__ float d_amv [ROWS_*NBC_];
__device__ int   d_ami [ROWS_*NBC_];

// ---------------- f32x2 packed math helpers ------------------------------------
__device__ __forceinline__ ull pk2(float x){
  ull r; asm("mov.b64 %0,{%1,%1};" : "=l"(r) : "f"(x)); return r;
}
__device__ __forceinline__ void fma2(ull &d, ull a, ull b){
  asm("fma.rn.f32x2 %0, %1, %2, %0;" : "+l"(d) : "l"(a), "l"(b));
}
__device__ __forceinline__ float2 up2(ull v){
  float2 f; asm("mov.b64 {%0,%1},%2;" : "=f"(f.x), "=f"(f.y) : "l"(v)); return f;
}

// ---------------- XLA-exact tanh (Eigen-style rational) ------------------------
__device__ __forceinline__ float tanh_xla(float x){
  float ax = fabsf(x);
  if (ax < 0.0004f) return x;
  float xc = fminf(fmaxf(x, -7.90531110763549805f), 7.90531110763549805f);
  float x2 = xc*xc;
  float p = fmaf(x2, -2.76076847742355e-16f, 2.00018790482477e-13f);
  p = fmaf(x2, p, -8.60467152213735e-11f);
  p = fmaf(x2, p,  5.12229709037114e-08f);
  p = fmaf(x2, p,  1.48572235717979e-05f);
  p = fmaf(x2, p,  6.37261928875436e-04f);
  p = fmaf(x2, p,  4.89352455891786e-03f);
  p = xc * p;
  float q = fmaf(x2, 1.19825839466702e-06f, 1.18534705686654e-04f);
  q = fmaf(x2, q, 2.26843463243900e-03f);
  q = fmaf(x2, q, 4.89352518554385e-03f);
  return p / q;
}
__device__ __forceinline__ float sigmoid_(float x){ return 0.5f + 0.5f*tanh_xla(0.5f*x); }

// ---------------- threefry2x32 (JAX partitionable) ----------------------------
__device__ __forceinline__ void tf2x32(unsigned k0, unsigned k1, unsigned x0, unsigned x1,
                                       unsigned &o0, unsigned &o1){
  unsigned k2 = k0 ^ k1 ^ 0x1BD11BDAu;
  x0 += k0; x1 += k1;
#define TFR(r) { x0 += x1; x1 = (x1<<(r)) | (x1>>(32-(r))); x1 ^= x0; }
  TFR(13) TFR(15) TFR(26) TFR(6)
  x0 += k1; x1 += k2 + 1u;
  TFR(17) TFR(29) TFR(16) TFR(24)
  x0 += k2; x1 += k0 + 2u;
  TFR(13) TFR(15) TFR(26) TFR(6)
  x0 += k0; x1 += k1 + 3u;
  TFR(17) TFR(29) TFR(16) TFR(24)
  x0 += k1; x1 += k2 + 4u;
  TFR(13) TFR(15) TFR(26) TFR(6)
  x0 += k2; x1 += k0 + 5u;
#undef TFR
  o0 = x0; o1 = x1;
}
__device__ __forceinline__ unsigned pbits(unsigned k0, unsigned k1, unsigned j){
  unsigned o0, o1; tf2x32(k0, k1, 0u, j, o0, o1); return o0 ^ o1;
}
__device__ __forceinline__ float gumbel_from_bits(unsigned bits){
  float f = __uint_as_float((bits>>9) | 0x3f800000u) - 1.0f;
  float u = fmaxf(TINYF, f + TINYF);
  return -logf(-logf(u));
}

// ---------------- init ---------------------------------------------------------
__global__ void k_init(const float* __restrict__ z, const float* __restrict__ emb){
  int i = blockIdx.x*blockDim.x + threadIdx.x;
  if (i < ROWS_*H_){
    d_A0T[DIN_*ROWS_ + i] = 0.f;    // h0^T = 0
    d_h1T[i] = 0.f;
    d_c0[i] = 0.f; d_c1[i] = 0.f;
  }
  if (i < Z_*ROWS_){                // z rows of A0T (constant across steps)
    int zz = i >> 6, r = i & 63;
    d_A0T[(E_+zz)*ROWS_ + r] = z[(r&31)*Z_ + zz];
  }
  if (i < E_*ROWS_){                // initial emb gather: START token (=1)
    int k = i >> 6, r = i & 63;
    d_A0T[(size_t)k*ROWS_ + r] = emb[(size_t)E_ + k];
  }
  if (i < B_) d_tok[i] = 1;
}

// ---- K-split GEMM: [64 x K]^T-stored A @ [K x 4096] W, f32x2, 8x4 tiles -------
// grid 256 = 64 col-tiles x 4 K-splits; block 128; tile 64r x 64c.
__global__ void __launch_bounds__(128) k_gemm(
    const float* __restrict__ A1, int alen1, const float* __restrict__ A2,
    const float* __restrict__ W1, int wlen1, const float* __restrict__ W2,
    int kPerSplit, float* __restrict__ gp)
{
  __shared__ float As[32][64];
  __shared__ float Ws[32][64];
  const int tid = threadIdx.x;
  const int ct = blockIdx.x & 63, sp = blockIdx.x >> 6;
  const int rg = tid >> 4, cg = tid & 15;
  const int kbeg = sp * kPerSplit;
  const int nch = kPerSplit >> 5;
  const int cbase = ct * 64;

  ull acc[8][2];
#pragma unroll
  for (int j=0;j<8;j++){ acc[j][0]=0ull; acc[j][1]=0ull; }

  float4 ra[4], rw[4];
  // prefetch chunk 0
  {
    int k0 = kbeg;
    const float* ap = (k0 < alen1) ? (A1 + (size_t)k0*64) : (A2 + (size_t)(k0-alen1)*64);
    const float* wp = (k0 < wlen1) ? (W1 + (size_t)k0*4096) : (W2 + (size_t)(k0-wlen1)*4096);
#pragma unroll
    for (int i=0;i<4;i++){
      int f = i*128 + tid;
      ra[i] = ((const float4*)ap)[f];
      int kk = f >> 4, c4 = (f & 15) * 4;
      rw[i] = *(const float4*)(wp + (size_t)kk*4096 + cbase + c4);
    }
  }
#pragma unroll
  for (int i=0;i<4;i++){
    int f = i*128 + tid, kk = f >> 4, c4 = (f & 15)*4;
    *(float4*)&As[kk][c4] = ra[i];
    *(float4*)&Ws[kk][c4] = rw[i];
  }
  __syncthreads();

  for (int ci = 0; ci < nch; ci++){
    if (ci+1 < nch){
      int k0 = kbeg + (ci+1)*32;
      const float* ap = (k0 < alen1) ? (A1 + (size_t)k0*64) : (A2 + (size_t)(k0-alen1)*64);
      const float* wp = (k0 < wlen1) ? (W1 + (size_t)k0*4096) : (W2 + (size_t)(k0-wlen1)*4096);
#pragma unroll
      for (int i=0;i<4;i++){
        int f = i*128 + tid;
        ra[i] = ((const float4*)ap)[f];
        int kk = f >> 4, c4 = (f & 15) * 4;
        rw[i] = *(const float4*)(wp + (size_t)kk*4096 + cbase + c4);
      }
    }
#pragma unroll
    for (int kk=0; kk<32; kk++){
      float4 a0 = *(const float4*)&As[kk][rg*8];
      float4 a1 = *(const float4*)&As[kk][rg*8+4];
      ulonglong2 w = *(const ulonglong2*)&Ws[kk][cg*4];
      ull pa;
      pa = pk2(a0.x); fma2(acc[0][0],pa,w.x); fma2(acc[0][1],pa,w.y);
      pa = pk2(a0.y); fma2(acc[1][0],pa,w.x); fma2(acc[1][1],pa,w.y);
      pa = pk2(a0.z); fma2(acc[2][0],pa,w.x); fma2(acc[2][1],pa,w.y);
      pa = pk2(a0.w); fma2(acc[3][0],pa,w.x); fma2(acc[3][1],pa,w.y);
      pa = pk2(a1.x); fma2(acc[4][0],pa,w.x); fma2(acc[4][1],pa,w.y);
      pa = pk2(a1.y); fma2(acc[5][0],pa,w.x); fma2(acc[5][1],pa,w.y);
      pa = pk2(a1.z); fma2(acc[6][0],pa,w.x); fma2(acc[6][1],pa,w.y);
      pa = pk2(a1.w); fma2(acc[7][0],pa,w.x); fma2(acc[7][1],pa,w.y);
    }
    __syncthreads();
    if (ci+1 < nch){
#pragma unroll
      for (int i=0;i<4;i++){
        int f = i*128 + tid, kk = f >> 4, c4 = (f & 15)*4;
        *(float4*)&As[kk][c4] = ra[i];
        *(float4*)&Ws[kk][c4] = rw[i];
      }
      __syncthreads();
    }
  }

  float* op = gp + (size_t)sp*ROWS_*4096;
#pragma unroll
  for (int j=0;j<8;j++){
    int r = rg*8 + j;
    float2 p0 = up2(acc[j][0]), p1 = up2(acc[j][1]);
    *(float4*)(op + (size_t)r*4096 + cbase + cg*4) = make_float4(p0.x,p0.y,p1.x,p1.y);
  }
}

// ---------------- bias + LSTM activation; writes h^T --------------------------
__global__ void __launch_bounds__(512) k_act(const float* __restrict__ b,
    float* __restrict__ c, float* __restrict__ hT)
{
  int idx = blockIdx.x*512 + threadIdx.x;      // 65536
  int h = idx & 1023, r = idx >> 10;
  const float* g0 = d_gp[0] + (size_t)r*4096;
  const float* g1 = d_gp[1] + (size_t)r*4096;
  const float* g2 = d_gp[2] + (size_t)r*4096;
  const float* g3 = d_gp[3] + (size_t)r*4096;
  float gi = ((g0[h]      + g1[h])      + (g2[h]      + g3[h]))      + b[h];
  float gf = ((g0[1024+h] + g1[1024+h]) + (g2[1024+h] + g3[1024+h])) + b[1024+h];
  float gg = ((g0[2048+h] + g1[2048+h]) + (g2[2048+h] + g3[2048+h])) + b[2048+h];
  float go = ((g0[3072+h] + g1[3072+h]) + (g2[3072+h] + g3[3072+h])) + b[3072+h];
  float cv = c[(size_t)r*1024 + h];
  float cn = sigmoid_(gf)*cv + sigmoid_(gi)*tanh_xla(gg);
  c[(size_t)r*1024 + h] = cn;
  hT[(size_t)h*64 + r]  = sigmoid_(go)*tanh_xla(cn);
}

// ---------------- logits GEMM + per-tile softmax partials ----------------------
// C[64,16000] = h1 @ Wout + bout; grid 250 col-tiles of 64; block 128; 8x4 tiles.
__global__ void __launch_bounds__(128) k_logits(
     const float* __restrict__ W, const float* __restrict__ bout)
{
  __shared__ float As[32][64];
  __shared__ float Ws[32][64];
  const int tid = threadIdx.x, cb = blockIdx.x;
  const int rg = tid >> 4, cg = tid & 15;
  const int cbase = cb * 64;

  ull acc[8][2];
#pragma unroll
  for (int j=0;j<8;j++){ acc[j][0]=0ull; acc[j][1]=0ull; }

  float4 ra[4], rw[4];
  {
#pragma unroll
    for (int i=0;i<4;i++){
      int f = i*128 + tid;
      ra[i] = ((const float4*)d_h1T)[f];
      int kk = f >> 4, c4 = (f & 15) * 4;
      rw[i] = *(const float4*)(W + (size_t)kk*V_ + cbase + c4);
    }
  }
#pragma unroll
  for (int i=0;i<4;i++){
    int f = i*128 + tid, kk = f >> 4, c4 = (f & 15)*4;
    *(float4*)&As[kk][c4] = ra[i];
    *(float4*)&Ws[kk][c4] = rw[i];
  }
  __syncthreads();

  for (int ci=0; ci<32; ci++){
    if (ci+1 < 32){
      int k0 = (ci+1)*32;
#pragma unroll
      for (int i=0;i<4;i++){
        int f = i*128 + tid;
        ra[i] = ((const float4*)(d_h1T + (size_t)k0*64))[f];
        int kk = f >> 4, c4 = (f & 15) * 4;
        rw[i] = *(const float4*)(W + (size_t)(k0+kk)*V_ + cbase + c4);
      }
    }
#pragma unroll
    for (int kk=0; kk<32; kk++){
      float4 a0 = *(const float4*)&As[kk][rg*8];
      float4 a1 = *(const float4*)&As[kk][rg*8+4];
      ulonglong2 w = *(const ulonglong2*)&Ws[kk][cg*4];
      ull pa;
      pa = pk2(a0.x); fma2(acc[0][0],pa,w.x); fma2(acc[0][1],pa,w.y);
      pa = pk2(a0.y); fma2(acc[1][0],pa,w.x); fma2(acc[1][1],pa,w.y);
      pa = pk2(a0.z); fma2(acc[2][0],pa,w.x); fma2(acc[2][1],pa,w.y);
      pa = pk2(a0.w); fma2(acc[3][0],pa,w.x); fma2(acc[3][1],pa,w.y);
      pa = pk2(a1.x); fma2(acc[4][0],pa,w.x); fma2(acc[4][1],pa,w.y);
      pa = pk2(a1.y); fma2(acc[5][0],pa,w.x); fma2(acc[5][1],pa,w.y);
      pa = pk2(a1.z); fma2(acc[6][0],pa,w.x); fma2(acc[6][1],pa,w.y);
      pa = pk2(a1.w); fma2(acc[7][0],pa,w.x); fma2(acc[7][1],pa,w.y);
    }
    __syncthreads();
    if (ci+1 < 32){
#pragma unroll
      for (int i=0;i<4;i++){
        int f = i*128 + tid, kk = f >> 4, c4 = (f & 15)*4;
        *(float4*)&As[kk][c4] = ra[i];
        *(float4*)&Ws[kk][c4] = rw[i];
      }
      __syncthreads();
    }
  }

  float4 bo = *(const float4*)(bout + cbase + cg*4);
#pragma unroll
  for (int j=0;j<8;j++){
    int row = rg*8 + j;
    float2 p0 = up2(acc[j][0]), p1 = up2(acc[j][1]);
    float v0 = p0.x + bo.x, v1 = p0.y + bo.y, v2 = p1.x + bo.z, v3 = p1.y + bo.w;
    float m = fmaxf(fmaxf(v0,v1), fmaxf(v2,v3));
#pragma unroll
    for (int msk=8; msk>=1; msk>>=1) m = fmaxf(m, __shfl_xor_sync(0xffffffffu, m, msk));
    float s = __expf(v0-m) + __expf(v1-m) + __expf(v2-m) + __expf(v3-m);
#pragma unroll
    for (int msk=8; msk>=1; msk>>=1) s += __shfl_xor_sync(0xffffffffu, s, msk);
    *(float4*)&d_logits[(size_t)row*V_ + cbase + cg*4] = make_float4(v0,v1,v2,v3);
    if (cg == 0){ d_pmax[row*NBCL_+cb] = m; d_psum[row*NBCL_+cb] = s; }
  }
}

// ---------------- p = exp(logp), gumbel sampling partial argmax -----------------
__global__ void __launch_bounds__(256) k_sample(int t, float* __restrict__ out)
{
  __shared__ float sM[ROWS_], sL[ROWS_];
  const int tid = threadIdx.x, cb = blockIdx.x;

  if (tid < ROWS_){
    float m = -INFINITY;
    for (int j=0;j<NBCL_;j++) m = fmaxf(m, d_pmax[tid*NBCL_+j]);
    float s = 0.f;
    for (int j=0;j<NBCL_;j++) s += d_psum[tid*NBCL_+j]*__expf(d_pmax[tid*NBCL_+j]-m);
    sM[tid] = m; sL[tid] = logf(s);
  }
  __syncthreads();

  const int pass = tid>>7, bp = (tid>>3)&15, sub = tid&7;
  unsigned ka0,ka1,k0,k1;
  tf2x32(0u, 42u, 0u, (unsigned)pass, ka0, ka1);
  tf2x32(ka0, ka1, 0u, (unsigned)t,  k0,  k1);

  const int rlo = pass*32 + bp, rhi = rlo + 16;
  const float Mlo = sM[rlo], Llo = sL[rlo], Mhi = sM[rhi], Lhi = sL[rhi];
  const float* __restrict__ loglo = d_logits + (size_t)rlo*V_;
  const float* __restrict__ loghi = d_logits + (size_t)rhi*V_;
  size_t baseLo = (pass==0) ? (size_t)O_PS + ((size_t)rlo*T_ + t)*V_
                            : (size_t)O_PF + ((size_t)(rlo-32)*T_ + t)*V_;
  size_t baseHi = (pass==0) ? (size_t)O_PS + ((size_t)rhi*T_ + t)*V_
                            : (size_t)O_PF + ((size_t)(rhi-32)*T_ + t)*V_;

  float bvlo = -INFINITY, bvhi = -INFINITY;
  int   bilo = 0x7fffffff, bihi = 0x7fffffff;

  for (int j=0;j<16;j++){
    int v = cb*128 + j*8 + sub;
    unsigned blo = pbits(k0, k1, (unsigned)(bp*V_ + v));
    unsigned bhi = pbits(k0, k1, (unsigned)((bp+16)*V_ + v));
    {
      float g = gumbel_from_bits(blo);
      float lp = (loglo[v] - Mlo) - Llo;
      out[baseLo + v] = __expf(lp);
      float val = lp + g;
      if (val > bvlo){ bvlo = val; bilo = v; }
    }
    {
      float g = gumbel_from_bits(bhi);
      float lp = (loghi[v] - Mhi) - Lhi;
      out[baseHi + v] = __expf(lp);
      float val = lp + g;
      if (val > bvhi){ bvhi = val; bihi = v; }
    }
  }
#pragma unroll
  for (int msk=4; msk>=1; msk>>=1){
    float ov; int oi;
    ov = __shfl_xor_sync(0xffffffffu, bvlo, msk);
    oi = __shfl_xor_sync(0xffffffffu, bilo, msk);
    if (ov > bvlo || (ov == bvlo && oi < bilo)){ bvlo = ov; bilo = oi; }
    ov = __shfl_xor_sync(0xffffffffu, bvhi, msk);
    oi = __shfl_xor_sync(0xffffffffu, bihi, msk);
    if (ov > bvhi || (ov == bvhi && oi < bihi)){ bvhi = ov; bihi = oi; }
  }
  if (sub == 0){
    d_amv[rlo*NBC_+cb] = bvlo; d_ami[rlo*NBC_+cb] = bilo;
    d_amv[rhi*NBC_+cb] = bvhi; d_ami[rhi*NBC_+cb] = bihi;
  }
}

// ------- final argmax + token update + NEXT step's embedding gather ------------
__global__ void __launch_bounds__(128) k_argprep(int t, const int* __restrict__ x,
    const float* __restrict__ emb, float* __restrict__ out)
{
  __shared__ float sv[128];
  __shared__ int   si[128];
  __shared__ int   stok;
  const int row = blockIdx.x, tid = threadIdx.x;
  sv[tid] = (tid < NBC_) ? d_amv[row*NBC_+tid] : -INFINITY;
  si[tid] = (tid < NBC_) ? d_ami[row*NBC_+tid] : 0x7fffffff;
  __syncthreads();
  for (int s=64; s>0; s>>=1){
    if (tid < s){
      float ov = sv[tid+s]; int oi = si[tid+s];
      if (ov > sv[tid] || (ov == sv[tid] && oi < si[tid])){ sv[tid]=ov; si[tid]=oi; }
    }
    __syncthreads();
  }
  if (tid == 0){
    int idx = si[0];
    int pass = row>>5, b = row&31;
    if (pass == 0){ out[(size_t)b*T_ + t] = (float)idx; d_tok[b] = idx; stok = idx; }
    else          { out[(size_t)O_SF + (size_t)b*T_ + t] = (float)idx;
                    stok = x[(size_t)b*T_ + t]; }
  }
  __syncthreads();
  const int tok = stok;
  for (int k = tid; k < E_; k += 128)
    d_A0T[(size_t)k*ROWS_ + row] = emb[(size_t)tok*E_ + k];
}

// ---------------- launch -------------------------------------------------------
extern "C" void kernel_launch(void* const* d_in, const int* in_sizes, int n_in,
                              void* d_out, int out_size)
{
  const int*   x    = (const int*)  d_in[0];
  const float* z    = (const float*)d_in[1];
  const float* emb  = (const float*)d_in[2];
  const float* Wx0  = (const float*)d_in[3];
  const float* Wh0  = (const float*)d_in[4];
  const float* b0   = (const float*)d_in[5];
  const float* Wx1  = (const float*)d_in[6];
  const float* Wh1  = (const float*)d_in[7];
  const float* b1   = (const float*)d_in[8];
  const float* Wout = (const float*)d_in[9];
  const float* bout = (const float*)d_in[10];
  float* out = (float*)d_out;

  float* pA0T; cudaGetSymbolAddress((void**)&pA0T, d_A0T);
  float* ph1T; cudaGetSymbolAddress((void**)&ph1T, d_h1T);
  float* pc0;  cudaGetSymbolAddress((void**)&pc0,  d_c0);
  float* pc1;  cudaGetSymbolAddress((void**)&pc1,  d_c1);
  float* pgp;  cudaGetSymbolAddress((void**)&pgp,  d_gp);

  k_init<<<256, 256>>>(z, emb);
  for (int t = 0; t < T_; t++){
    // LSTM0: A = A0T (len 1664), W = [Wx0;Wh0] split at 640; K/4 = 416
    k_gemm<<<256, 128>>>(pA0T, 1<<30, (const float*)nullptr,
                         Wx0, DIN_, Wh0, 416, pgp);
    k_act <<<128, 512>>>(b0, pc0, pA0T + (size_t)DIN_*ROWS_);
    // LSTM1: A = [h0T; h1T] split at 1024, W = [Wx1;Wh1] split at 1024; K/4 = 512
    k_gemm<<<256, 128>>>(pA0T + (size_t)DIN_*ROWS_, H_, ph1T,
                         Wx1, H_, Wh1, 512, pgp);
    k_act <<<128, 512>>>(b1, pc1, ph1T);
    k_logits<<<NBCL_, 128>>>(Wout, bout);
    k_sample<<<NBC_, 256>>>(t, out);
    k_argprep<<<ROWS_, 128>>>(t, x, emb, out);
  }
}

// round 6
// speedup vs baseline: 3.0172x; 1.0199x over previous
#include <cuda_runtime.h>
#include <math.h>
#include <stdint.h>

typedef unsigned long long ull;

// Problem constants
#define B_    32
#define T_    128
#define V_    16000
#define E_    512
#define Z_    128
#define H_    1024
#define DIN_  640        // E+Z
#define ROWS_ 64         // 32 sample-pass rows + 32 teacher-forced rows
#define NBC_  125        // 16000/128 sampling col tiles
#define NBCL_ 500        // 16000/32 logits col tiles
#define TINYF 1.17549435e-38f

// Output layout (float32): [s_s (B*T)] [p_s (B*T*V)] [s_f (B*T)] [p_f (B*T*V)]
#define O_PS  4096
#define O_SF  65540096
#define O_PF  65544192

// ---------------- device scratch (static globals; no allocations) -------------
__device__ float d_A0T[(DIN_+H_)*ROWS_];    // [k][64r]; emb rows, z rows, h0^T
__device__ float d_h1T[H_*ROWS_];
__device__ float d_c0[ROWS_*H_];
__device__ float d_c1[ROWS_*H_];
__device__ float d_gp[16][ROWS_*4*H_];      // K-split gate partials (up to 16)
__device__ int   d_tok[B_];
__device__ float d_logits[ROWS_*V_];
__device__ float d_pmax[ROWS_*NBCL_];
__device__ float d_psum[ROWS_*NBCL_];
__device__ float d_amv [ROWS_*NBC_];
__device__ int   d_ami [ROWS_*NBC_];

// ---------------- f32x2 packed math helpers ------------------------------------
__device__ __forceinline__ ull pk2(float x){
  ull r; asm("mov.b64 %0,{%1,%1};" : "=l"(r) : "f"(x)); return r;
}
__device__ __forceinline__ void fma2(ull &d, ull a, ull b){
  asm("fma.rn.f32x2 %0, %1, %2, %0;" : "+l"(d) : "l"(a), "l"(b));
}
__device__ __forceinline__ float2 up2(ull v){
  float2 f; asm("mov.b64 {%0,%1},%2;" : "=f"(f.x), "=f"(f.y) : "l"(v)); return f;
}

// ---------------- XLA-exact tanh (Eigen-style rational) ------------------------
__device__ __forceinline__ float tanh_xla(float x){
  float ax = fabsf(x);
  if (ax < 0.0004f) return x;
  float xc = fminf(fmaxf(x, -7.90531110763549805f), 7.90531110763549805f);
  float x2 = xc*xc;
  float p = fmaf(x2, -2.76076847742355e-16f, 2.00018790482477e-13f);
  p = fmaf(x2, p, -8.60467152213735e-11f);
  p = fmaf(x2, p,  5.12229709037114e-08f);
  p = fmaf(x2, p,  1.48572235717979e-05f);
  p = fmaf(x2, p,  6.37261928875436e-04f);
  p = fmaf(x2, p,  4.89352455891786e-03f);
  p = xc * p;
  float q = fmaf(x2, 1.19825839466702e-06f, 1.18534705686654e-04f);
  q = fmaf(x2, q, 2.26843463243900e-03f);
  q = fmaf(x2, q, 4.89352518554385e-03f);
  return p / q;
}
__device__ __forceinline__ float sigmoid_(float x){ return 0.5f + 0.5f*tanh_xla(0.5f*x); }

// ---------------- threefry2x32 (JAX partitionable) ----------------------------
__device__ __forceinline__ void tf2x32(unsigned k0, unsigned k1, unsigned x0, unsigned x1,
                                       unsigned &o0, unsigned &o1){
  unsigned k2 = k0 ^ k1 ^ 0x1BD11BDAu;
  x0 += k0; x1 += k1;
#define TFR(r) { x0 += x1; x1 = (x1<<(r)) | (x1>>(32-(r))); x1 ^= x0; }
  TFR(13) TFR(15) TFR(26) TFR(6)
  x0 += k1; x1 += k2 + 1u;
  TFR(17) TFR(29) TFR(16) TFR(24)
  x0 += k2; x1 += k0 + 2u;
  TFR(13) TFR(15) TFR(26) TFR(6)
  x0 += k0; x1 += k1 + 3u;
  TFR(17) TFR(29) TFR(16) TFR(24)
  x0 += k1; x1 += k2 + 4u;
  TFR(13) TFR(15) TFR(26) TFR(6)
  x0 += k2; x1 += k0 + 5u;
#undef TFR
  o0 = x0; o1 = x1;
}
__device__ __forceinline__ unsigned pbits(unsigned k0, unsigned k1, unsigned j){
  unsigned o0, o1; tf2x32(k0, k1, 0u, j, o0, o1); return o0 ^ o1;
}
__device__ __forceinline__ float gumbel_from_bits(unsigned bits){
  float f = __uint_as_float((bits>>9) | 0x3f800000u) - 1.0f;
  float u = fmaxf(TINYF, f + TINYF);
  return -logf(-logf(u));
}

// ---------------- init ---------------------------------------------------------
__global__ void k_init(const float* __restrict__ z, const float* __restrict__ emb){
  int i = blockIdx.x*blockDim.x + threadIdx.x;
  if (i < ROWS_*H_){
    d_A0T[DIN_*ROWS_ + i] = 0.f;    // h0^T = 0
    d_h1T[i] = 0.f;
    d_c0[i] = 0.f; d_c1[i] = 0.f;
  }
  if (i < Z_*ROWS_){                // z rows of A0T (constant across steps)
    int zz = i >> 6, r = i & 63;
    d_A0T[(E_+zz)*ROWS_ + r] = z[(r&31)*Z_ + zz];
  }
  if (i < E_*ROWS_){                // initial emb gather: START token (=1)
    int k = i >> 6, r = i & 63;
    d_A0T[(size_t)k*ROWS_ + r] = emb[(size_t)E_ + k];
  }
  if (i < B_) d_tok[i] = 1;
}

// ---- K-split GEMM: [64 x K]^T-stored A @ [K x 4096] W, f32x2, 8x4 tiles -------
// grid = 64 col-tiles x NSPLIT; block 128; each split does 4 chunks (128 k-rows).
__global__ void __launch_bounds__(128) k_gemm(
    const float* __restrict__ A1, int alen1, const float* __restrict__ A2,
    const float* __restrict__ W1, int wlen1, const float* __restrict__ W2,
    float* __restrict__ gp)
{
  __shared__ float As[32][64];
  __shared__ float Ws[32][64];
  const int tid = threadIdx.x;
  const int ct = blockIdx.x & 63, sp = blockIdx.x >> 6;
  const int rg = tid >> 4, cg = tid & 15;
  const int kbeg = sp * 128;
  const int nch = 4;
  const int cbase = ct * 64;

  ull acc[8][2];
#pragma unroll
  for (int j=0;j<8;j++){ acc[j][0]=0ull; acc[j][1]=0ull; }

  float4 ra[4], rw[4];
  {
    int k0 = kbeg;
    const float* ap = (k0 < alen1) ? (A1 + (size_t)k0*64) : (A2 + (size_t)(k0-alen1)*64);
    const float* wp = (k0 < wlen1) ? (W1 + (size_t)k0*4096) : (W2 + (size_t)(k0-wlen1)*4096);
#pragma unroll
    for (int i=0;i<4;i++){
      int f = i*128 + tid;
      ra[i] = ((const float4*)ap)[f];
      int kk = f >> 4, c4 = (f & 15) * 4;
      rw[i] = *(const float4*)(wp + (size_t)kk*4096 + cbase + c4);
    }
  }
#pragma unroll
  for (int i=0;i<4;i++){
    int f = i*128 + tid, kk = f >> 4, c4 = (f & 15)*4;
    *(float4*)&As[kk][c4] = ra[i];
    *(float4*)&Ws[kk][c4] = rw[i];
  }
  __syncthreads();

  for (int ci = 0; ci < nch; ci++){
    if (ci+1 < nch){
      int k0 = kbeg + (ci+1)*32;
      const float* ap = (k0 < alen1) ? (A1 + (size_t)k0*64) : (A2 + (size_t)(k0-alen1)*64);
      const float* wp = (k0 < wlen1) ? (W1 + (size_t)k0*4096) : (W2 + (size_t)(k0-wlen1)*4096);
#pragma unroll
      for (int i=0;i<4;i++){
        int f = i*128 + tid;
        ra[i] = ((const float4*)ap)[f];
        int kk = f >> 4, c4 = (f & 15) * 4;
        rw[i] = *(const float4*)(wp + (size_t)kk*4096 + cbase + c4);
      }
    }
#pragma unroll
    for (int kk=0; kk<32; kk++){
      float4 a0 = *(const float4*)&As[kk][rg*8];
      float4 a1 = *(const float4*)&As[kk][rg*8+4];
      ulonglong2 w = *(const ulonglong2*)&Ws[kk][cg*4];
      ull pa;
      pa = pk2(a0.x); fma2(acc[0][0],pa,w.x); fma2(acc[0][1],pa,w.y);
      pa = pk2(a0.y); fma2(acc[1][0],pa,w.x); fma2(acc[1][1],pa,w.y);
      pa = pk2(a0.z); fma2(acc[2][0],pa,w.x); fma2(acc[2][1],pa,w.y);
      pa = pk2(a0.w); fma2(acc[3][0],pa,w.x); fma2(acc[3][1],pa,w.y);
      pa = pk2(a1.x); fma2(acc[4][0],pa,w.x); fma2(acc[4][1],pa,w.y);
      pa = pk2(a1.y); fma2(acc[5][0],pa,w.x); fma2(acc[5][1],pa,w.y);
      pa = pk2(a1.z); fma2(acc[6][0],pa,w.x); fma2(acc[6][1],pa,w.y);
      pa = pk2(a1.w); fma2(acc[7][0],pa,w.x); fma2(acc[7][1],pa,w.y);
    }
    __syncthreads();
    if (ci+1 < nch){
#pragma unroll
      for (int i=0;i<4;i++){
        int f = i*128 + tid, kk = f >> 4, c4 = (f & 15)*4;
        *(float4*)&As[kk][c4] = ra[i];
        *(float4*)&Ws[kk][c4] = rw[i];
      }
      __syncthreads();
    }
  }

  float* op = gp + (size_t)sp*ROWS_*4096;
#pragma unroll
  for (int j=0;j<8;j++){
    int r = rg*8 + j;
    float2 p0 = up2(acc[j][0]), p1 = up2(acc[j][1]);
    *(float4*)(op + (size_t)r*4096 + cbase + cg*4) = make_float4(p0.x,p0.y,p1.x,p1.y);
  }
}

// ---------------- bias + LSTM activation; writes h^T --------------------------
__global__ void __launch_bounds__(512) k_act(int nsplit, const float* __restrict__ b,
    float* __restrict__ c, float* __restrict__ hT)
{
  int idx = blockIdx.x*512 + threadIdx.x;      // 65536
  int h = idx & 1023, r = idx >> 10;
  size_t base = (size_t)r*4096;
  float gi = b[h], gf = b[1024+h], gg = b[2048+h], go = b[3072+h];
  for (int s = 0; s < nsplit; s++){
    const float* g = d_gp[s] + base;
    gi += g[h]; gf += g[1024+h]; gg += g[2048+h]; go += g[3072+h];
  }
  float cv = c[(size_t)r*1024 + h];
  float cn = sigmoid_(gf)*cv + sigmoid_(gi)*tanh_xla(gg);
  c[(size_t)r*1024 + h] = cn;
  hT[(size_t)h*64 + r]  = sigmoid_(go)*tanh_xla(cn);
}

// ---------------- logits GEMM + per-tile softmax partials ----------------------
// C[64,16000]; grid 500 col-tiles of 32; block 128; per-thread 8 rows x 2 cols.
__global__ void __launch_bounds__(128) k_logits(
     const float* __restrict__ W, const float* __restrict__ bout)
{
  __shared__ float As[32][64];
  __shared__ float Ws[32][32];
  const int tid = threadIdx.x, cb = blockIdx.x;
  const int rg = tid >> 4, cg = tid & 15;
  const int cbase = cb * 32;

  ull acc[8];
#pragma unroll
  for (int j=0;j<8;j++) acc[j]=0ull;

  float4 ra[4], rw[2];
  {
#pragma unroll
    for (int i=0;i<4;i++) ra[i] = ((const float4*)d_h1T)[i*128 + tid];
#pragma unroll
    for (int i=0;i<2;i++){
      int f = i*128 + tid, kk = f >> 3, c4 = (f & 7) * 4;
      rw[i] = *(const float4*)(W + (size_t)kk*V_ + cbase + c4);
    }
  }
#pragma unroll
  for (int i=0;i<4;i++){
    int f = i*128 + tid, kk = f >> 4, c4 = (f & 15)*4;
    *(float4*)&As[kk][c4] = ra[i];
  }
#pragma unroll
  for (int i=0;i<2;i++){
    int f = i*128 + tid, kk = f >> 3, c4 = (f & 7)*4;
    *(float4*)&Ws[kk][c4] = rw[i];
  }
  __syncthreads();

  for (int ci=0; ci<32; ci++){
    if (ci+1 < 32){
      int k0 = (ci+1)*32;
#pragma unroll
      for (int i=0;i<4;i++) ra[i] = ((const float4*)(d_h1T + (size_t)k0*64))[i*128 + tid];
#pragma unroll
      for (int i=0;i<2;i++){
        int f = i*128 + tid, kk = f >> 3, c4 = (f & 7) * 4;
        rw[i] = *(const float4*)(W + (size_t)(k0+kk)*V_ + cbase + c4);
      }
    }
#pragma unroll
    for (int kk=0; kk<32; kk++){
      float4 a0 = *(const float4*)&As[kk][rg*8];
      float4 a1 = *(const float4*)&As[kk][rg*8+4];
      ull w = *(const ull*)&Ws[kk][cg*2];
      fma2(acc[0], pk2(a0.x), w);
      fma2(acc[1], pk2(a0.y), w);
      fma2(acc[2], pk2(a0.z), w);
      fma2(acc[3], pk2(a0.w), w);
      fma2(acc[4], pk2(a1.x), w);
      fma2(acc[5], pk2(a1.y), w);
      fma2(acc[6], pk2(a1.z), w);
      fma2(acc[7], pk2(a1.w), w);
    }
    __syncthreads();
    if (ci+1 < 32){
#pragma unroll
      for (int i=0;i<4;i++){
        int f = i*128 + tid, kk = f >> 4, c4 = (f & 15)*4;
        *(float4*)&As[kk][c4] = ra[i];
      }
#pragma unroll
      for (int i=0;i<2;i++){
        int f = i*128 + tid, kk = f >> 3, c4 = (f & 7)*4;
        *(float4*)&Ws[kk][c4] = rw[i];
      }
      __syncthreads();
    }
  }

  float2 bo = *(const float2*)(bout + cbase + cg*2);
#pragma unroll
  for (int j=0;j<8;j++){
    int row = rg*8 + j;
    float2 p = up2(acc[j]);
    float v0 = p.x + bo.x, v1 = p.y + bo.y;
    float m = fmaxf(v0, v1);
#pragma unroll
    for (int msk=8; msk>=1; msk>>=1) m = fmaxf(m, __shfl_xor_sync(0xffffffffu, m, msk));
    float s = __expf(v0-m) + __expf(v1-m);
#pragma unroll
    for (int msk=8; msk>=1; msk>>=1) s += __shfl_xor_sync(0xffffffffu, s, msk);
    *(float2*)&d_logits[(size_t)row*V_ + cbase + cg*2] = make_float2(v0,v1);
    if (cg == 0){ d_pmax[row*NBCL_+cb] = m; d_psum[row*NBCL_+cb] = s; }
  }
}

// ------- p = exp(logp), gumbel sampling partial argmax (inline row-LSE) --------
__global__ void __launch_bounds__(256) k_sample(int t, float* __restrict__ out)
{
  __shared__ float sM[ROWS_], sL[ROWS_];
  __shared__ float tmpM[4][ROWS_], tmpS[4][ROWS_];
  const int tid = threadIdx.x, cb = blockIdx.x;

  // Phase 1: parallel row log-sum-exp over 500 tiles (4 threads per row)
  {
    const int row = tid & 63, part = tid >> 6;
    const float* pm = d_pmax + (size_t)row*NBCL_;
    const float* ps = d_psum + (size_t)row*NBCL_;
    float m = -INFINITY;
    for (int j = part*125; j < (part+1)*125; j++) m = fmaxf(m, pm[j]);
    tmpM[part][row] = m;
    __syncthreads();
    float M = fmaxf(fmaxf(tmpM[0][row], tmpM[1][row]), fmaxf(tmpM[2][row], tmpM[3][row]));
    float s = 0.f;
    for (int j = part*125; j < (part+1)*125; j++) s += ps[j]*__expf(pm[j]-M);
    tmpS[part][row] = s;
    __syncthreads();
    if (part == 0){
      sM[row] = M;
      sL[row] = logf((tmpS[0][row]+tmpS[1][row]) + (tmpS[2][row]+tmpS[3][row]));
    }
    __syncthreads();
  }

  const int pass = tid>>7, bp = (tid>>3)&15, sub = tid&7;
  unsigned ka0,ka1,k0,k1;
  tf2x32(0u, 42u, 0u, (unsigned)pass, ka0, ka1);
  tf2x32(ka0, ka1, 0u, (unsigned)t,  k0,  k1);

  const int rlo = pass*32 + bp, rhi = rlo + 16;
  const float Mlo = sM[rlo], Llo = sL[rlo], Mhi = sM[rhi], Lhi = sL[rhi];
  const float* __restrict__ loglo = d_logits + (size_t)rlo*V_;
  const float* __restrict__ loghi = d_logits + (size_t)rhi*V_;
  size_t baseLo = (pass==0) ? (size_t)O_PS + ((size_t)rlo*T_ + t)*V_
                            : (size_t)O_PF + ((size_t)(rlo-32)*T_ + t)*V_;
  size_t baseHi = (pass==0) ? (size_t)O_PS + ((size_t)rhi*T_ + t)*V_
                            : (size_t)O_PF + ((size_t)(rhi-32)*T_ + t)*V_;

  float bvlo = -INFINITY, bvhi = -INFINITY;
  int   bilo = 0x7fffffff, bihi = 0x7fffffff;

  for (int j=0;j<16;j++){
    int v = cb*128 + j*8 + sub;
    unsigned blo = pbits(k0, k1, (unsigned)(bp*V_ + v));
    unsigned bhi = pbits(k0, k1, (unsigned)((bp+16)*V_ + v));
    {
      float g = gumbel_from_bits(blo);
      float lp = (loglo[v] - Mlo) - Llo;
      out[baseLo + v] = __expf(lp);
      float val = lp + g;
      if (val > bvlo){ bvlo = val; bilo = v; }
    }
    {
      float g = gumbel_from_bits(bhi);
      float lp = (loghi[v] - Mhi) - Lhi;
      out[baseHi + v] = __expf(lp);
      float val = lp + g;
      if (val > bvhi){ bvhi = val; bihi = v; }
    }
  }
#pragma unroll
  for (int msk=4; msk>=1; msk>>=1){
    float ov; int oi;
    ov = __shfl_xor_sync(0xffffffffu, bvlo, msk);
    oi = __shfl_xor_sync(0xffffffffu, bilo, msk);
    if (ov > bvlo || (ov == bvlo && oi < bilo)){ bvlo = ov; bilo = oi; }
    ov = __shfl_xor_sync(0xffffffffu, bvhi, msk);
    oi = __shfl_xor_sync(0xffffffffu, bihi, msk);
    if (ov > bvhi || (ov == bvhi && oi < bihi)){ bvhi = ov; bihi = oi; }
  }
  if (sub == 0){
    d_amv[rlo*NBC_+cb] = bvlo; d_ami[rlo*NBC_+cb] = bilo;
    d_amv[rhi*NBC_+cb] = bvhi; d_ami[rhi*NBC_+cb] = bihi;
  }
}

// ------- final argmax + token update + NEXT step's embedding gather ------------
__global__ void __launch_bounds__(128) k_argprep(int t, const int* __restrict__ x,
    const float* __restrict__ emb, float* __restrict__ out)
{
  __shared__ float sv[128];
  __shared__ int   si[128];
  __shared__ int   stok;
  const int row = blockIdx.x, tid = threadIdx.x;
  sv[tid] = (tid < NBC_) ? d_amv[row*NBC_+tid] : -INFINITY;
  si[tid] = (tid < NBC_) ? d_ami[row*NBC_+tid] : 0x7fffffff;
  __syncthreads();
  for (int s=64; s>0; s>>=1){
    if (tid < s){
      float ov = sv[tid+s]; int oi = si[tid+s];
      if (ov > sv[tid] || (ov == sv[tid] && oi < si[tid])){ sv[tid]=ov; si[tid]=oi; }
    }
    __syncthreads();
  }
  if (tid == 0){
    int idx = si[0];
    int pass = row>>5, b = row&31;
    if (pass == 0){ out[(size_t)b*T_ + t] = (float)idx; d_tok[b] = idx; stok = idx; }
    else          { out[(size_t)O_SF + (size_t)b*T_ + t] = (float)idx;
                    stok = x[(size_t)b*T_ + t]; }
  }
  __syncthreads();
  const int tok = stok;
  for (int k = tid; k < E_; k += 128)
    d_A0T[(size_t)k*ROWS_ + row] = emb[(size_t)tok*E_ + k];
}

// ---------------- launch -------------------------------------------------------
extern "C" void kernel_launch(void* const* d_in, const int* in_sizes, int n_in,
                              void* d_out, int out_size)
{
  const int*   x    = (const int*)  d_in[0];
  const float* z    = (const float*)d_in[1];
  const float* emb  = (const float*)d_in[2];
  const float* Wx0  = (const float*)d_in[3];
  const float* Wh0  = (const float*)d_in[4];
  const float* b0   = (const float*)d_in[5];
  const float* Wx1  = (const float*)d_in[6];
  const float* Wh1  = (const float*)d_in[7];
  const float* b1   = (const float*)d_in[8];
  const float* Wout = (const float*)d_in[9];
  const float* bout = (const float*)d_in[10];
  float* out = (float*)d_out;

  float* pA0T; cudaGetSymbolAddress((void**)&pA0T, d_A0T);
  float* ph1T; cudaGetSymbolAddress((void**)&ph1T, d_h1T);
  float* pc0;  cudaGetSymbolAddress((void**)&pc0,  d_c0);
  float* pc1;  cudaGetSymbolAddress((void**)&pc1,  d_c1);
  float* pgp;  cudaGetSymbolAddress((void**)&pgp,  d_gp);

  k_init<<<256, 256>>>(z, emb);
  for (int t = 0; t < T_; t++){
    // LSTM0: K=1664 = 13 splits x 128; grid 64*13
    k_gemm<<<64*13, 128>>>(pA0T, 1<<30, (const float*)nullptr,
                           Wx0, DIN_, Wh0, pgp);
    k_act <<<128, 512>>>(13, b0, pc0, pA0T + (size_t)DIN_*ROWS_);
    // LSTM1: K=2048 = 16 splits x 128; grid 64*16
    k_gemm<<<64*16, 128>>>(pA0T + (size_t)DIN_*ROWS_, H_, ph1T,
                           Wx1, H_, Wh1, pgp);
    k_act <<<128, 512>>>(16, b1, pc1, ph1T);
    k_logits<<<NBCL_, 128>>>(Wout, bout);
    k_sample<<<NBC_, 256>>>(t, out);
    k_argprep<<<ROWS_, 128>>>(t, x, emb, out);
  }
}

// round 7
// speedup vs baseline: 3.6488x; 1.2093x over previous
#include <cuda_runtime.h>
#include <math.h>
#include <stdint.h>

typedef unsigned long long ull;

// Problem constants
#define B_    32
#define T_    128
#define V_    16000
#define E_    512
#define Z_    128
#define H_    1024
#define DIN_  640        // E+Z
#define ROWS_ 64         // 32 sample-pass rows + 32 teacher-forced rows
#define NBCL_ 500        // 16000/32 logits col tiles
#define TINYF 1.17549435e-38f

// Output layout (float32): [s_s (B*T)] [p_s (B*T*V)] [s_f (B*T)] [p_f (B*T*V)]
#define O_PS  4096
#define O_SF  65540096
#define O_PF  65544192

// ---------------- device scratch (static globals; no allocations) -------------
__device__ float d_A0T[(DIN_+H_)*ROWS_];    // [k][64r]; emb rows, z rows, h0^T
__device__ float d_h1T[H_*ROWS_];
__device__ float d_c0[ROWS_*H_];
__device__ float d_c1[ROWS_*H_];
__device__ float d_gp[16][ROWS_*4*H_];      // K-split gate partials (up to 16)
__device__ int   d_tok[B_];
__device__ float d_logits[ROWS_*V_];
__device__ float d_pmax[ROWS_*NBCL_];
__device__ float d_psum[ROWS_*NBCL_];
__device__ float d_rM[ROWS_];
__device__ float d_rL[ROWS_];
__device__ float d_amv [ROWS_*NBCL_];
__device__ int   d_ami [ROWS_*NBCL_];

// ---------------- f32x2 packed math helpers ------------------------------------
__device__ __forceinline__ ull pk2(float x){
  ull r; asm("mov.b64 %0,{%1,%1};" : "=l"(r) : "f"(x)); return r;
}
__device__ __forceinline__ void fma2(ull &d, ull a, ull b){
  asm("fma.rn.f32x2 %0, %1, %2, %0;" : "+l"(d) : "l"(a), "l"(b));
}
__device__ __forceinline__ float2 up2(ull v){
  float2 f; asm("mov.b64 {%0,%1},%2;" : "=f"(f.x), "=f"(f.y) : "l"(v)); return f;
}

// ---------------- cp.async helpers ---------------------------------------------
__device__ __forceinline__ unsigned su32(const void* p){
  return (unsigned)__cvta_generic_to_shared(p);
}
__device__ __forceinline__ void cpa16(unsigned s, const void* g){
  asm volatile("cp.async.ca.shared.global [%0], [%1], 16;" :: "r"(s), "l"(g));
}
__device__ __forceinline__ void cp_commit(){ asm volatile("cp.async.commit_group;"); }
__device__ __forceinline__ void cp_wait1(){ asm volatile("cp.async.wait_group 1;"); }
__device__ __forceinline__ void cp_wait0(){ asm volatile("cp.async.wait_group 0;"); }

// ---------------- XLA-exact tanh (Eigen-style rational) ------------------------
__device__ __forceinline__ float tanh_xla(float x){
  float ax = fabsf(x);
  if (ax < 0.0004f) return x;
  float xc = fminf(fmaxf(x, -7.90531110763549805f), 7.90531110763549805f);
  float x2 = xc*xc;
  float p = fmaf(x2, -2.76076847742355e-16f, 2.00018790482477e-13f);
  p = fmaf(x2, p, -8.60467152213735e-11f);
  p = fmaf(x2, p,  5.12229709037114e-08f);
  p = fmaf(x2, p,  1.48572235717979e-05f);
  p = fmaf(x2, p,  6.37261928875436e-04f);
  p = fmaf(x2, p,  4.89352455891786e-03f);
  p = xc * p;
  float q = fmaf(x2, 1.19825839466702e-06f, 1.18534705686654e-04f);
  q = fmaf(x2, q, 2.26843463243900e-03f);
  q = fmaf(x2, q, 4.89352518554385e-03f);
  return p / q;
}
__device__ __forceinline__ float sigmoid_(float x){ return 0.5f + 0.5f*tanh_xla(0.5f*x); }

// ---------------- threefry2x32 (JAX partitionable) ----------------------------
__device__ __forceinline__ void tf2x32(unsigned k0, unsigned k1, unsigned x0, unsigned x1,
                                       unsigned &o0, unsigned &o1){
  unsigned k2 = k0 ^ k1 ^ 0x1BD11BDAu;
  x0 += k0; x1 += k1;
#define TFR(r) { x0 += x1; x1 = (x1<<(r)) | (x1>>(32-(r))); x1 ^= x0; }
  TFR(13) TFR(15) TFR(26) TFR(6)
  x0 += k1; x1 += k2 + 1u;
  TFR(17) TFR(29) TFR(16) TFR(24)
  x0 += k2; x1 += k0 + 2u;
  TFR(13) TFR(15) TFR(26) TFR(6)
  x0 += k0; x1 += k1 + 3u;
  TFR(17) TFR(29) TFR(16) TFR(24)
  x0 += k1; x1 += k2 + 4u;
  TFR(13) TFR(15) TFR(26) TFR(6)
  x0 += k2; x1 += k0 + 5u;
#undef TFR
  o0 = x0; o1 = x1;
}
__device__ __forceinline__ unsigned pbits(unsigned k0, unsigned k1, unsigned j){
  unsigned o0, o1; tf2x32(k0, k1, 0u, j, o0, o1); return o0 ^ o1;
}
__device__ __forceinline__ float gumbel_from_bits(unsigned bits){
  float f = __uint_as_float((bits>>9) | 0x3f800000u) - 1.0f;
  float u = fmaxf(TINYF, f + TINYF);
  return -logf(-logf(u));
}

// ---------------- init ---------------------------------------------------------
__global__ void k_init(const float* __restrict__ z, const float* __restrict__ emb){
  int i = blockIdx.x*blockDim.x + threadIdx.x;
  if (i < ROWS_*H_){
    d_A0T[DIN_*ROWS_ + i] = 0.f;    // h0^T = 0
    d_h1T[i] = 0.f;
    d_c0[i] = 0.f; d_c1[i] = 0.f;
  }
  if (i < Z_*ROWS_){                // z rows of A0T (constant across steps)
    int zz = i >> 6, r = i & 63;
    d_A0T[(E_+zz)*ROWS_ + r] = z[(r&31)*Z_ + zz];
  }
  if (i < E_*ROWS_){                // initial emb gather: START token (=1)
    int k = i >> 6, r = i & 63;
    d_A0T[(size_t)k*ROWS_ + r] = emb[(size_t)E_ + k];
  }
  if (i < B_) d_tok[i] = 1;
}

// ---- K-split GEMM: [64 x K]^T-stored A @ [K x 4096] W, f32x2, cp.async --------
// grid = 64 col-tiles x NSPLIT; block 128; each split = 4 chunks of 32 k-rows.
__global__ void __launch_bounds__(128) k_gemm(
    const float* __restrict__ A1, int alen1, const float* __restrict__ A2,
    const float* __restrict__ W1, int wlen1, const float* __restrict__ W2,
    float* __restrict__ gp)
{
  __shared__ float As[2][32*64];
  __shared__ float Ws[2][32*64];
  const int tid = threadIdx.x;
  const int ct = blockIdx.x & 63, sp = blockIdx.x >> 6;
  const int rg = tid >> 4, cg = tid & 15;
  const int kbeg = sp * 128;
  const int cbase = ct * 64;

  const unsigned sA0 = su32(&As[0][0]), sA1 = su32(&As[1][0]);
  const unsigned sW0 = su32(&Ws[0][0]), sW1 = su32(&Ws[1][0]);

  // stage issue: A chunk is linear [32*64]; W float4 f -> (kk=f>>4, c=(f&15)*4)
#define ISSUE(sa, sw, K0) {                                                  \
    const float* ap = ((K0) < alen1) ? (A1 + (size_t)(K0)*64)                \
                                     : (A2 + (size_t)((K0)-alen1)*64);       \
    const float* wp = ((K0) < wlen1) ? (W1 + (size_t)(K0)*4096)              \
                                     : (W2 + (size_t)((K0)-wlen1)*4096);     \
    _Pragma("unroll")                                                        \
    for (int i=0;i<4;i++){                                                   \
      int f = i*128 + tid;                                                   \
      cpa16((sa) + f*16, ap + f*4);                                          \
      int kk = f >> 4, c4 = (f & 15) * 4;                                    \
      cpa16((sw) + f*16, wp + (size_t)kk*4096 + cbase + c4);                 \
    }                                                                        \
    cp_commit(); }

  ull acc[8][2];
#pragma unroll
  for (int j=0;j<8;j++){ acc[j][0]=0ull; acc[j][1]=0ull; }

  ISSUE(sA0, sW0, kbeg)
  ISSUE(sA1, sW1, kbeg+32)

#pragma unroll
  for (int ci = 0; ci < 4; ci++){
    if (ci < 3) cp_wait1(); else cp_wait0();
    __syncthreads();
    const float* Ac = &As[ci&1][0];
    const float* Wc = &Ws[ci&1][0];
#pragma unroll
    for (int kk=0; kk<32; kk++){
      float4 a0 = *(const float4*)(Ac + kk*64 + rg*8);
      float4 a1 = *(const float4*)(Ac + kk*64 + rg*8 + 4);
      ulonglong2 w = *(const ulonglong2*)(Wc + kk*64 + cg*4);
      ull pa;
      pa = pk2(a0.x); fma2(acc[0][0],pa,w.x); fma2(acc[0][1],pa,w.y);
      pa = pk2(a0.y); fma2(acc[1][0],pa,w.x); fma2(acc[1][1],pa,w.y);
      pa = pk2(a0.z); fma2(acc[2][0],pa,w.x); fma2(acc[2][1],pa,w.y);
      pa = pk2(a0.w); fma2(acc[3][0],pa,w.x); fma2(acc[3][1],pa,w.y);
      pa = pk2(a1.x); fma2(acc[4][0],pa,w.x); fma2(acc[4][1],pa,w.y);
      pa = pk2(a1.y); fma2(acc[5][0],pa,w.x); fma2(acc[5][1],pa,w.y);
      pa = pk2(a1.z); fma2(acc[6][0],pa,w.x); fma2(acc[6][1],pa,w.y);
      pa = pk2(a1.w); fma2(acc[7][0],pa,w.x); fma2(acc[7][1],pa,w.y);
    }
    __syncthreads();
    if (ci+2 < 4){
      if ((ci&1)==0){ ISSUE(sA0, sW0, kbeg+(ci+2)*32) }
      else          { ISSUE(sA1, sW1, kbeg+(ci+2)*32) }
    }
  }

  float* op = gp + (size_t)sp*ROWS_*4096;
#pragma unroll
  for (int j=0;j<8;j++){
    int r = rg*8 + j;
    float2 p0 = up2(acc[j][0]), p1 = up2(acc[j][1]);
    *(float4*)(op + (size_t)r*4096 + cbase + cg*4) = make_float4(p0.x,p0.y,p1.x,p1.y);
  }
#undef ISSUE
}

// ---------------- bias + LSTM activation; writes h^T --------------------------
__global__ void __launch_bounds__(512) k_act(int nsplit, const float* __restrict__ b,
    float* __restrict__ c, float* __restrict__ hT)
{
  int idx = blockIdx.x*512 + threadIdx.x;      // 65536
  int h = idx & 1023, r = idx >> 10;
  size_t base = (size_t)r*4096;
  float gi = b[h], gf = b[1024+h], gg = b[2048+h], go = b[3072+h];
  for (int s = 0; s < nsplit; s++){
    const float* g = d_gp[s] + base;
    gi += g[h]; gf += g[1024+h]; gg += g[2048+h]; go += g[3072+h];
  }
  float cv = c[(size_t)r*1024 + h];
  float cn = sigmoid_(gf)*cv + sigmoid_(gi)*tanh_xla(gg);
  c[(size_t)r*1024 + h] = cn;
  hT[(size_t)h*64 + r]  = sigmoid_(go)*tanh_xla(cn);
}

// ------- logits GEMM + bias + tile softmax partials + Gumbel tile argmax -------
// grid 500 col-tiles of 32; block 128; per-thread 8 rows x 2 cols; cp.async.
__global__ void __launch_bounds__(128) k_logits(int t,
     const float* __restrict__ W, const float* __restrict__ bout)
{
  __shared__ float As[2][32*64];
  __shared__ float Ws[2][32*32];
  const int tid = threadIdx.x, cb = blockIdx.x;
  const int rg = tid >> 4, cg = tid & 15;
  const int cbase = cb * 32;

  const unsigned sA0 = su32(&As[0][0]), sA1 = su32(&As[1][0]);
  const unsigned sW0 = su32(&Ws[0][0]), sW1 = su32(&Ws[1][0]);

#define LISSUE(sa, sw, K0) {                                                 \
    const float* ap = d_h1T + (size_t)(K0)*64;                               \
    _Pragma("unroll")                                                        \
    for (int i=0;i<4;i++){ int f = i*128 + tid; cpa16((sa)+f*16, ap + f*4); }\
    _Pragma("unroll")                                                        \
    for (int i=0;i<2;i++){                                                   \
      int f = i*128 + tid, kk = f >> 3, c4 = (f & 7) * 4;                    \
      cpa16((sw)+f*16, W + (size_t)((K0)+kk)*V_ + cbase + c4);               \
    }                                                                        \
    cp_commit(); }

  ull acc[8];
#pragma unroll
  for (int j=0;j<8;j++) acc[j]=0ull;

  LISSUE(sA0, sW0, 0)
  LISSUE(sA1, sW1, 32)

  for (int ci=0; ci<32; ci++){
    if (ci < 31) cp_wait1(); else cp_wait0();
    __syncthreads();
    const float* Ac = &As[ci&1][0];
    const float* Wc = &Ws[ci&1][0];
#pragma unroll
    for (int kk=0; kk<32; kk++){
      float4 a0 = *(const float4*)(Ac + kk*64 + rg*8);
      float4 a1 = *(const float4*)(Ac + kk*64 + rg*8 + 4);
      ull w = *(const ull*)(Wc + kk*32 + cg*2);
      fma2(acc[0], pk2(a0.x), w);
      fma2(acc[1], pk2(a0.y), w);
      fma2(acc[2], pk2(a0.z), w);
      fma2(acc[3], pk2(a0.w), w);
      fma2(acc[4], pk2(a1.x), w);
      fma2(acc[5], pk2(a1.y), w);
      fma2(acc[6], pk2(a1.z), w);
      fma2(acc[7], pk2(a1.w), w);
    }
    __syncthreads();
    if (ci+2 < 32){
      if ((ci&1)==0){ LISSUE(sA0, sW0, (ci+2)*32) }
      else          { LISSUE(sA1, sW1, (ci+2)*32) }
    }
  }
#undef LISSUE

  // RNG keys for both passes (stream 0 = free-running rows 0-31, 1 = teacher)
  unsigned k0p[2], k1p[2];
  { unsigned a0,a1; tf2x32(0u,42u,0u,0u,a0,a1); tf2x32(a0,a1,0u,(unsigned)t,k0p[0],k1p[0]); }
  { unsigned a0,a1; tf2x32(0u,42u,0u,1u,a0,a1); tf2x32(a0,a1,0u,(unsigned)t,k0p[1],k1p[1]); }

  float2 bo = *(const float2*)(bout + cbase + cg*2);
  const int c0 = cbase + cg*2, c1 = c0 + 1;
#pragma unroll
  for (int j=0;j<8;j++){
    int row = rg*8 + j;
    int pass = row >> 5, bb = row & 31;
    float2 p = up2(acc[j]);
    float v0 = p.x + bo.x, v1 = p.y + bo.y;
    // tile max / exp-sum partials (over the 16 cg lanes = 32 cols)
    float m = fmaxf(v0, v1);
#pragma unroll
    for (int msk=8; msk>=1; msk>>=1) m = fmaxf(m, __shfl_xor_sync(0xffffffffu, m, msk));
    float s = __expf(v0-m) + __expf(v1-m);
#pragma unroll
    for (int msk=8; msk>=1; msk>>=1) s += __shfl_xor_sync(0xffffffffu, s, msk);
    // Gumbel perturbation + tile argmax (row-constant shift drops out of argmax)
    float g0 = gumbel_from_bits(pbits(k0p[pass], k1p[pass], (unsigned)(bb*V_ + c0)));
    float g1 = gumbel_from_bits(pbits(k0p[pass], k1p[pass], (unsigned)(bb*V_ + c1)));
    float t0 = v0 + g0, t1 = v1 + g1;
    float bv = t0; int bi = c0;
    if (t1 > bv){ bv = t1; bi = c1; }
#pragma unroll
    for (int msk=8; msk>=1; msk>>=1){
      float ov = __shfl_xor_sync(0xffffffffu, bv, msk);
      int   oi = __shfl_xor_sync(0xffffffffu, bi, msk);
      if (ov > bv || (ov == bv && oi < bi)){ bv = ov; bi = oi; }
    }
    *(float2*)&d_logits[(size_t)row*V_ + c0] = make_float2(v0,v1);
    if (cg == 0){
      d_pmax[row*NBCL_+cb] = m; d_psum[row*NBCL_+cb] = s;
      d_amv [row*NBCL_+cb] = bv; d_ami [row*NBCL_+cb] = bi;
    }
  }
}

// -- per-row: LSE over 500 tiles, global argmax, token update, emb gather -------
__global__ void __launch_bounds__(256) k_argprep(int t, const int* __restrict__ x,
    const float* __restrict__ emb, float* __restrict__ out)
{
  __shared__ float sm[256], ss[256], sv[256];
  __shared__ int   si[256];
  __shared__ int   stok;
  const int row = blockIdx.x, tid = threadIdx.x;
  const float* pm = d_pmax + (size_t)row*NBCL_;
  const float* ps = d_psum + (size_t)row*NBCL_;

  float m = -INFINITY;
  for (int j=tid; j<NBCL_; j+=256) m = fmaxf(m, pm[j]);
  sm[tid] = m; __syncthreads();
  for (int k=128;k>0;k>>=1){ if (tid<k) sm[tid]=fmaxf(sm[tid],sm[tid+k]); __syncthreads(); }
  const float M = sm[0];
  float s = 0.f;
  for (int j=tid; j<NBCL_; j+=256) s += ps[j]*__expf(pm[j]-M);
  ss[tid] = s; __syncthreads();
  for (int k=128;k>0;k>>=1){ if (tid<k) ss[tid]+=ss[tid+k]; __syncthreads(); }
  if (tid == 0){ d_rM[row] = M; d_rL[row] = logf(ss[0]); }

  float bv = -INFINITY; int bi = 0x7fffffff;
  for (int j=tid; j<NBCL_; j+=256){
    float v = d_amv[(size_t)row*NBCL_+j]; int ii = d_ami[(size_t)row*NBCL_+j];
    if (v > bv || (v == bv && ii < bi)){ bv = v; bi = ii; }
  }
  sv[tid] = bv; si[tid] = bi; __syncthreads();
  for (int k=128;k>0;k>>=1){
    if (tid<k){
      float ov = sv[tid+k]; int oi = si[tid+k];
      if (ov > sv[tid] || (ov == sv[tid] && oi < si[tid])){ sv[tid]=ov; si[tid]=oi; }
    }
    __syncthreads();
  }
  if (tid == 0){
    int idx = si[0];
    int pass = row>>5, b = row&31;
    if (pass == 0){ out[(size_t)b*T_ + t] = (float)idx; d_tok[b] = idx; stok = idx; }
    else          { out[(size_t)O_SF + (size_t)b*T_ + t] = (float)idx;
                    stok = x[(size_t)b*T_ + t]; }
  }
  __syncthreads();
  const int tok = stok;
  for (int k = tid; k < E_; k += 256)
    d_A0T[(size_t)k*ROWS_ + row] = emb[(size_t)tok*E_ + k];
}

// ---------------- p = exp(logit - M - L) writer --------------------------------
// grid 250 tiles of 64 cols; block 256; 4 float4 per thread.
__global__ void __launch_bounds__(256) k_pwrite(int t, float* __restrict__ out)
{
  const int tid = threadIdx.x, cb = blockIdx.x;
  const int cbase = cb * 64;
#pragma unroll
  for (int i=0;i<4;i++){
    int e = i*256 + tid;
    int row = e >> 4, c4 = (e & 15) * 4;
    float ML = d_rM[row] + d_rL[row];
    float4 lg = *(const float4*)&d_logits[(size_t)row*V_ + cbase + c4];
    float4 pv = make_float4(__expf(lg.x-ML), __expf(lg.y-ML),
                            __expf(lg.z-ML), __expf(lg.w-ML));
    int pass = row>>5, b = row&31;
    size_t base = (pass==0) ? (size_t)O_PS + ((size_t)b*T_ + t)*V_
                            : (size_t)O_PF + ((size_t)b*T_ + t)*V_;
    *(float4*)&out[base + cbase + c4] = pv;
  }
}

// ---------------- launch -------------------------------------------------------
extern "C" void kernel_launch(void* const* d_in, const int* in_sizes, int n_in,
                              void* d_out, int out_size)
{
  const int*   x    = (const int*)  d_in[0];
  const float* z    = (const float*)d_in[1];
  const float* emb  = (const float*)d_in[2];
  const float* Wx0  = (const float*)d_in[3];
  const float* Wh0  = (const float*)d_in[4];
  const float* b0   = (const float*)d_in[5];
  const float* Wx1  = (const float*)d_in[6];
  const float* Wh1  = (const float*)d_in[7];
  const float* b1   = (const float*)d_in[8];
  const float* Wout = (const float*)d_in[9];
  const float* bout = (const float*)d_in[10];
  float* out = (float*)d_out;

  float* pA0T; cudaGetSymbolAddress((void**)&pA0T, d_A0T);
  float* ph1T; cudaGetSymbolAddress((void**)&ph1T, d_h1T);
  float* pc0;  cudaGetSymbolAddress((void**)&pc0,  d_c0);
  float* pc1;  cudaGetSymbolAddress((void**)&pc1,  d_c1);
  float* pgp;  cudaGetSymbolAddress((void**)&pgp,  d_gp);

  k_init<<<256, 256>>>(z, emb);
  for (int t = 0; t < T_; t++){
    // LSTM0: K=1664 = 13 splits x 128
    k_gemm<<<64*13, 128>>>(pA0T, 1<<30, (const float*)nullptr,
                           Wx0, DIN_, Wh0, pgp);
    k_act <<<128, 512>>>(13, b0, pc0, pA0T + (size_t)DIN_*ROWS_);
    // LSTM1: K=2048 = 16 splits x 128
    k_gemm<<<64*16, 128>>>(pA0T + (size_t)DIN_*ROWS_, H_, ph1T,
                           Wx1, H_, Wh1, pgp);
    k_act <<<128, 512>>>(16, b1, pc1, ph1T);
    k_logits<<<NBCL_, 128>>>(t, Wout, bout);
    k_argprep<<<ROWS_, 256>>>(t, x, emb, out);
    k_pwrite<<<250, 256>>>(t, out);
  }
}